// round 13
// baseline (speedup 1.0000x reference)
#include <cuda_runtime.h>
#include <cuda_bf16.h>
#include <cstdint>

#define NB     16
#define SEQ    512
#define DMODEL 512
#define MAXF   2048

#define UMAX   36864L    // pair capacity of U arrays (Yp 16384 + Ye 16384 + Yd 4096)

// ---------------- scratch (static __device__ arrays: allowed) ----------------
__device__ __align__(128) float g_Hexp[NB * MAXF * DMODEL];   // fp32 Hexp
__device__ __align__(128) float g_Yp  [NB * MAXF * DMODEL];   // pp layer1 out (fp32)
__device__ __align__(128) float g_Ye  [NB * MAXF * DMODEL];   // ep layer1 out
__device__ __align__(128) float g_Yd  [NB * SEQ  * DMODEL];   // dp layer1 out
// Winograd input transform, hi/lo bf16: [pt][pair][ch]
__device__ __align__(128) __nv_bfloat16 g_Uhi[4 * UMAX * 512];
__device__ __align__(128) __nv_bfloat16 g_Ulo[4 * UMAX * 512];
// Winograd-transformed weights: [conv][pt][f][c], hi/lo bf16
__device__ __align__(128) __nv_bfloat16 g_Vhi[6 * 4 * 512 * 512];
__device__ __align__(128) __nv_bfloat16 g_Vlo[6 * 4 * 512 * 512];
#define TOTROWS (2 * NB * MAXF + NB * SEQ)   // pp | ep | dp output rows
__device__ float g_part[TOTROWS * 4];
__device__ int   g_idx [NB * MAXF];

// ================= baseline-ISA helpers (compute_103-safe) =================
__device__ __forceinline__ uint32_t smem_to_u32(const void* p) {
    uint32_t a;
    asm("{ .reg .u64 t; cvta.to.shared.u64 t, %1; cvt.u32.u64 %0, t; }" : "=r"(a) : "l"(p));
    return a;
}
__device__ __forceinline__ void cpasync16(uint32_t dst, const void* src) {
    asm volatile("cp.async.cg.shared.global [%0], [%1], 16;" :: "r"(dst), "l"(src));
}
#define CP_COMMIT() asm volatile("cp.async.commit_group;" ::: "memory")
#define CP_WAIT1()  asm volatile("cp.async.wait_group 1;"  ::: "memory")

__device__ __forceinline__ void ldmx4(uint32_t* r, uint32_t addr) {
    asm volatile("ldmatrix.sync.aligned.m8n8.x4.shared.b16 {%0,%1,%2,%3}, [%4];"
                 : "=r"(r[0]), "=r"(r[1]), "=r"(r[2]), "=r"(r[3]) : "r"(addr));
}
__device__ __forceinline__ void mma16816(float* d, const uint32_t* a, const uint32_t* b) {
    asm volatile("mma.sync.aligned.m16n8k16.row.col.f32.bf16.bf16.f32 "
                 "{%0,%1,%2,%3}, {%4,%5,%6,%7}, {%8,%9}, {%0,%1,%2,%3};"
                 : "+f"(d[0]), "+f"(d[1]), "+f"(d[2]), "+f"(d[3])
                 : "r"(a[0]), "r"(a[1]), "r"(a[2]), "r"(a[3]), "r"(b[0]), "r"(b[1]));
}
__device__ __forceinline__ uint32_t pack2bf(float a, float b) {
    __nv_bfloat162 t = __floats2bfloat162_rn(a, b);
    return *reinterpret_cast<uint32_t*>(&t);
}
// packed smem tile: 4 rows per 128B line (16ch bf16 = 2 x 16B segs), XOR swizzle
#define TADDR16(r, s) ((uint32_t)((((r) >> 2) * 128) + ((((((r) & 3) << 1) | (s)) ^ (((r) >> 2) & 7)) << 4)))

// ---------------- Winograd weight transform + hi/lo split ----------------
__global__ void wtrans_wino_kernel(const float* __restrict__ w0p, const float* __restrict__ w1p,
                                   const float* __restrict__ w2p, const float* __restrict__ w3p,
                                   const float* __restrict__ w4p, const float* __restrict__ w5p) {
    int conv = blockIdx.x >> 9;
    int f    = blockIdx.x & 511;
    int c    = threadIdx.x;
    const float* w = conv == 0 ? w0p : conv == 1 ? w1p : conv == 2 ? w2p :
                     conv == 3 ? w3p : conv == 4 ? w4p : w5p;
    float w0 = w[(f * 512 + c) * 3 + 0];
    float w1 = w[(f * 512 + c) * 3 + 1];
    float w2 = w[(f * 512 + c) * 3 + 2];
    float V[4] = {w0, 0.5f * (w0 + w1 + w2), 0.5f * (w0 - w1 + w2), w2};
#pragma unroll
    for (int pt = 0; pt < 4; pt++) {
        long o = ((long)(conv * 4 + pt) * 512 + f) * 512 + c;
        __nv_bfloat16 h = __float2bfloat16(V[pt]);
        g_Vhi[o] = h;
        g_Vlo[o] = __float2bfloat16(V[pt] - __bfloat162float(h));
    }
}

// ---------------- Winograd input transform pre-pass (merged over <=3 inputs) ----------------
// pair pg -> rows 2p-1..2p+2 (zero-padded at batch edges) -> U0..U3 hi/lo bf16
__global__ void utrans_kernel(const float* __restrict__ A0, int S0, int P0,
                              const float* __restrict__ A1, int S1, int P1,
                              const float* __restrict__ A2, int S2, int P2) {
    int pg = blockIdx.x;
    const float* X; int S, pl;
    if (pg < P0)           { X = A0; S = S0; pl = pg; }
    else if (pg < P0 + P1) { X = A1; S = S1; pl = pg - P0; }
    else                   { X = A2; S = S2; pl = pg - P0 - P1; }
    const int ppb = S >> 1;
    const int b = pl / ppb;
    const int p = pl - b * ppb;
    const float* Xb = X + (long)b * S * 512;
    const int c = threadIdx.x * 4;

    float4 d[4];
#pragma unroll
    for (int k = 0; k < 4; k++) {
        int s = 2 * p - 1 + k;
        d[k] = (s >= 0 && s < S) ? *(const float4*)&Xb[(long)s * 512 + c]
                                 : make_float4(0.f, 0.f, 0.f, 0.f);
    }
    float U[4][4];
    U[0][0] = d[0].x - d[2].x; U[0][1] = d[0].y - d[2].y; U[0][2] = d[0].z - d[2].z; U[0][3] = d[0].w - d[2].w;
    U[1][0] = d[1].x + d[2].x; U[1][1] = d[1].y + d[2].y; U[1][2] = d[1].z + d[2].z; U[1][3] = d[1].w + d[2].w;
    U[2][0] = d[2].x - d[1].x; U[2][1] = d[2].y - d[1].y; U[2][2] = d[2].z - d[1].z; U[2][3] = d[2].w - d[1].w;
    U[3][0] = d[1].x - d[3].x; U[3][1] = d[1].y - d[3].y; U[3][2] = d[1].z - d[3].z; U[3][3] = d[1].w - d[3].w;
#pragma unroll
    for (int pt = 0; pt < 4; pt++) {
        float h[4], l[4];
#pragma unroll
        for (int k = 0; k < 4; k++) {
            __nv_bfloat16 hb = __float2bfloat16(U[pt][k]);
            h[k] = __bfloat162float(hb);
            l[k] = U[pt][k] - h[k];
        }
        long base = ((long)pt * UMAX + pg) * 512 + c;
        uint2 hv, lv;
        hv.x = pack2bf(h[0], h[1]); hv.y = pack2bf(h[2], h[3]);
        lv.x = pack2bf(l[0], l[1]); lv.y = pack2bf(l[2], l[3]);
        *(uint2*)&g_Uhi[base] = hv;
        *(uint2*)&g_Ulo[base] = lv;
    }
}

// ---------------- duration cumsum + searchsorted ----------------
__global__ void duration_idx_kernel(const int* __restrict__ Dgt) {
    __shared__ int cs[512];
    int b = blockIdx.x, tid = threadIdx.x;
    int v = Dgt[b * 512 + tid];
    cs[tid] = v > 0 ? v : 0;
    __syncthreads();
    for (int off = 1; off < 512; off <<= 1) {
        int add = (tid >= off) ? cs[tid - off] : 0;
        __syncthreads();
        cs[tid] += add;
        __syncthreads();
    }
    int total = cs[511];
    int Tmax  = total < MAXF ? total : MAXF;
    for (int t = tid; t < MAXF; t += 512) {
        int r;
        if (t >= Tmax) {
            r = -1;
        } else {
            int lo = 0, hi = 511;
            while (lo < hi) {
                int mid = (lo + hi) >> 1;
                if (cs[mid] > t) hi = mid; else lo = mid + 1;
            }
            r = lo;
        }
        g_idx[b * MAXF + t] = r;
    }
}

// ---------------- gather H_exp (fp32) + fused variance adapt ----------------
__global__ void gather_adapt_kernel(const float* __restrict__ H,
                                    const float* __restrict__ P,
                                    const float* __restrict__ E,
                                    const float* __restrict__ pw,
                                    const float* __restrict__ pb,
                                    const float* __restrict__ ew,
                                    const float* __restrict__ eb,
                                    float* __restrict__ outH) {
    int bt  = blockIdx.x;
    int b   = bt >> 11;
    int idx = g_idx[bt];
    int d   = threadIdx.x * 4;
    float4 h = make_float4(0.f, 0.f, 0.f, 0.f);
    if (idx >= 0) h = *(const float4*)&H[((long)(b * 512 + idx)) * 512 + d];
    long xo = (long)bt * 512 + d;
    *(float4*)&g_Hexp[xo] = h;

    float p = P[bt], e = E[bt];
    float4 pw4 = *(const float4*)&pw[d];
    float4 pb4 = *(const float4*)&pb[d];
    float4 ew4 = *(const float4*)&ew[d];
    float4 eb4 = *(const float4*)&eb[d];
    float4 o;
    o.x = h.x + p * pw4.x + pb4.x + e * ew4.x + eb4.x;
    o.y = h.y + p * pw4.y + pb4.y + e * ew4.y + eb4.y;
    o.z = h.z + p * pw4.z + pb4.z + e * ew4.z + eb4.z;
    o.w = h.w + p * pw4.w + pb4.w + e * ew4.w + eb4.w;
    *(float4*)&outH[xo] = o;
}

// noop: pads launch count so ncu -s 5 -c 1 profiles the layer-1 conv
__global__ void noop_kernel() {}

// ---------------- Winograd F(2,3) conv, pure-GEMM mainloop (R7 regime) ----------------
// Merged pp+ep+dp. Grid (4, 576): y<256 pp, <512 ep, else dp.
// CTA: 64 pairs x 128 filters, 512 threads (16 warps, 4M x 4N, warp 16pr x 32f).
// 32 iters of 16-ch chunks; A and B both cp.async, ring-3, one barrier/iter.
// Per iter per warp: 4 pts x (2 A-ldmx4 + 4 B-ldmx4 + 12 MMA).
// LAYER=1: Y = relu(conv+bias) fp32.  LAYER=2: fused wl-dot -> g_part.
#define A_PT    4096                 // per point: hi 2048 | lo 2048 (64 pairs x 16ch)
#define A_BUF   16384                // 4 points
#define B_BASE  49152                // after 3 A buffers
#define B_PT    8192                 // per point: hi 4096 | lo 4096 (128 f x 16ch)
#define B_SLOT  32768                // 4 points
#define DSM_TOT (B_BASE + 3 * B_SLOT)   // 147456

template <int LAYER>
__global__ __launch_bounds__(512, 1)
void conv_wino_kernel(const float* __restrict__ b_pp, const float* __restrict__ b_ep,
                      const float* __restrict__ b_dp, const float* __restrict__ wl_pp,
                      const float* __restrict__ wl_ep, const float* __restrict__ wl_dp) {
    extern __shared__ char sm[];
    const uint32_t sb = smem_to_u32(sm);
    __shared__ float s_bias[128];
    __shared__ float s_wl[128];
    __shared__ float s_part[128][4];

    const int tid  = threadIdx.x;
    const int lane = tid & 31;
    const int wid  = tid >> 5;
    const int warpM = wid & 3, warpN = wid >> 2;
    const int rowW = warpM * 16;        // pair rows within 64
    const int colW = warpN * 32;

    // ---- job decode ----
    const int y = blockIdx.y;
    int job, yl;
    if (y < 256)      { job = 0; yl = y; }
    else if (y < 512) { job = 1; yl = y - 256; }
    else              { job = 2; yl = y - 512; }
    // U pair offsets: layer1: Hexp at 0 (pp+ep), H at 16384 (dp)
    //                 layer2: Yp 0, Ye 16384, Yd 32768
    long pairOff;
    int conv;
    if (LAYER == 1) {
        pairOff = (job == 2) ? 16384 + (long)yl * 64 : (long)yl * 64;
        conv    = job == 0 ? 2 : job == 1 ? 4 : 0;
    } else {
        pairOff = (long)job * 16384 + (long)yl * 64;   // job==2 -> 32768
        conv    = job == 0 ? 3 : job == 1 ? 5 : 1;
    }
    const float* bias = job == 0 ? b_pp : job == 1 ? b_ep : b_dp;
    const float* wl   = job == 0 ? wl_pp : job == 1 ? wl_ep : wl_dp;
    float* Yout = job == 0 ? g_Yp : job == 1 ? g_Ye : g_Yd;
    const long rowOff = job == 0 ? 0 : job == 1 ? (long)NB * MAXF : 2L * NB * MAXF;

    const int fBase = blockIdx.x * 128;
    const __nv_bfloat16* VhC = g_Vhi + ((long)(conv * 4) * 512 + fBase) * 512;
    const __nv_bfloat16* VlC = g_Vlo + ((long)(conv * 4) * 512 + fBase) * 512;

    if (tid < 128) {
        s_bias[tid] = bias[fBase + tid];
        if (LAYER == 2) s_wl[tid] = wl[fBase + tid];
    }

    // ---- stage A chunk: 4 pts x 64 pairs x 16 ch, hi/lo ----
    auto stageA = [&](int it) {
        const int c0 = it << 4;
        const uint32_t abuf = sb + (it % 3) * A_BUF;
#pragma unroll
        for (int q = 0; q < 2; q++) {
            int idx = tid + q * 512;          // 0..1023
            int pt = idx >> 8, rem = idx & 255;
            int r = rem >> 2, hl = (rem >> 1) & 1, s = rem & 1;
            const __nv_bfloat16* src = (hl ? g_Ulo : g_Uhi) +
                (((long)pt * UMAX + pairOff + r) * 512 + c0 + s * 8);
            cpasync16(abuf + pt * A_PT + hl * 2048 + TADDR16(r, s), src);
        }
    };
    // ---- stage B chunk: 4 pts x 128 filters x 16 ch, hi/lo ----
    auto stageB = [&](int it) {
        const int c0 = it << 4;
        const uint32_t bbuf = sb + B_BASE + (it % 3) * B_SLOT;
#pragma unroll
        for (int q = 0; q < 4; q++) {
            int idx = tid + q * 512;          // 0..2047
            int pt = idx >> 9, rem = idx & 511;
            int r = rem >> 2, hl = (rem >> 1) & 1, s = rem & 1;
            const __nv_bfloat16* src = (hl ? VlC : VhC) +
                ((long)pt * 512 * 512 + (long)r * 512 + c0 + s * 8);
            cpasync16(bbuf + pt * B_PT + hl * 4096 + TADDR16(r, s), src);
        }
    };

    // ---- per-lane ldmatrix bases (R12-proven mapping) ----
    const int q = lane >> 3;
    const int am = rowW + ((q & 1) << 3) + (lane & 7);
    const int ac16b = q >> 1;
    int an[2];
#pragma unroll
    for (int np = 0; np < 2; np++) an[np] = colW + np * 16 + ((q >> 1) << 3) + (lane & 7);
    const int bc16b = q & 1;
    const uint32_t aOff = TADDR16(am, ac16b);
    uint32_t bOff[2];
#pragma unroll
    for (int np = 0; np < 2; np++) bOff[np] = TADDR16(an[np], bc16b);

    float acc[4][4][4];                 // [point][ntile][frag]
#pragma unroll
    for (int pt = 0; pt < 4; pt++)
#pragma unroll
        for (int nt = 0; nt < 4; nt++)
#pragma unroll
            for (int v = 0; v < 4; v++) acc[pt][nt][v] = 0.f;

    stageA(0); stageB(0); CP_COMMIT();
    stageA(1); stageB(1); CP_COMMIT();

    for (int it = 0; it < 32; it++) {
        CP_WAIT1();
        __syncthreads();
        const uint32_t aBuf = sb + (it % 3) * A_BUF;
        const uint32_t bBuf = sb + B_BASE + (it % 3) * B_SLOT;

#pragma unroll
        for (int pt = 0; pt < 4; pt++) {
            uint32_t ah[4], al[4];
            ldmx4(ah, aBuf + pt * A_PT + aOff);
            ldmx4(al, aBuf + pt * A_PT + 2048 + aOff);
            uint32_t bh[4][2], bl[4][2];
#pragma unroll
            for (int np = 0; np < 2; np++) {
                uint32_t t[4];
                ldmx4(t, bBuf + pt * B_PT + bOff[np]);
                bh[2 * np][0] = t[0]; bh[2 * np][1] = t[1];
                bh[2 * np + 1][0] = t[2]; bh[2 * np + 1][1] = t[3];
                ldmx4(t, bBuf + pt * B_PT + 4096 + bOff[np]);
                bl[2 * np][0] = t[0]; bl[2 * np][1] = t[1];
                bl[2 * np + 1][0] = t[2]; bl[2 * np + 1][1] = t[3];
            }
#pragma unroll
            for (int nt = 0; nt < 4; nt++) mma16816(acc[pt][nt], ah, bh[nt]);
#pragma unroll
            for (int nt = 0; nt < 4; nt++) mma16816(acc[pt][nt], ah, bl[nt]);
#pragma unroll
            for (int nt = 0; nt < 4; nt++) mma16816(acc[pt][nt], al, bh[nt]);
        }

        if (it + 2 < 32) { stageA(it + 2); stageB(it + 2); }
        CP_COMMIT();
    }

    // ---------------- epilogue: output transform + bias + relu ----------------
    const int tq = lane >> 2;
    const int tr = lane & 3;
    if (LAYER == 1) {
#pragma unroll
        for (int nt = 0; nt < 4; nt++) {
            const int cl = colW + nt * 8 + 2 * tr;
            const float b0 = s_bias[cl], b1 = s_bias[cl + 1];
#pragma unroll
            for (int h = 0; h < 2; h++) {
                const long P = (long)yl * 64 + rowW + tq + 8 * h;   // pair within job
                const int v0 = 2 * h, v1 = 2 * h + 1;
                float m0a = acc[0][nt][v0], m1a = acc[1][nt][v0],
                      m2a = acc[2][nt][v0], m3a = acc[3][nt][v0];
                float m0b = acc[0][nt][v1], m1b = acc[1][nt][v1],
                      m2b = acc[2][nt][v1], m3b = acc[3][nt][v1];
                float y0a = fmaxf(m0a + m1a + m2a + b0, 0.f);
                float y0b = fmaxf(m0b + m1b + m2b + b1, 0.f);
                float y1a = fmaxf(m1a - m2a - m3a + b0, 0.f);
                float y1b = fmaxf(m1b - m2b - m3b + b1, 0.f);
                *(float2*)&Yout[(2 * P)     * 512 + fBase + cl] = make_float2(y0a, y0b);
                *(float2*)&Yout[(2 * P + 1) * 512 + fBase + cl] = make_float2(y1a, y1b);
            }
        }
    } else {
        float s00 = 0.f, s10 = 0.f, s01 = 0.f, s11 = 0.f;
#pragma unroll
        for (int nt = 0; nt < 4; nt++) {
            const int cl = colW + nt * 8 + 2 * tr;
            const float b0 = s_bias[cl], b1 = s_bias[cl + 1];
            const float w0 = s_wl[cl], w1 = s_wl[cl + 1];
#pragma unroll
            for (int h = 0; h < 2; h++) {
                const int v0 = 2 * h, v1 = 2 * h + 1;
                float m0a = acc[0][nt][v0], m1a = acc[1][nt][v0],
                      m2a = acc[2][nt][v0], m3a = acc[3][nt][v0];
                float m0b = acc[0][nt][v1], m1b = acc[1][nt][v1],
                      m2b = acc[2][nt][v1], m3b = acc[3][nt][v1];
                float sy0 = fmaxf(m0a + m1a + m2a + b0, 0.f) * w0
                          + fmaxf(m0b + m1b + m2b + b1, 0.f) * w1;
                float sy1 = fmaxf(m1a - m2a - m3a + b0, 0.f) * w0
                          + fmaxf(m1b - m2b - m3b + b1, 0.f) * w1;
                if (h == 0) { s00 += sy0; s10 += sy1; }
                else        { s01 += sy0; s11 += sy1; }
            }
        }
        s00 += __shfl_xor_sync(0xFFFFFFFF, s00, 1);
        s00 += __shfl_xor_sync(0xFFFFFFFF, s00, 2);
        s10 += __shfl_xor_sync(0xFFFFFFFF, s10, 1);
        s10 += __shfl_xor_sync(0xFFFFFFFF, s10, 2);
        s01 += __shfl_xor_sync(0xFFFFFFFF, s01, 1);
        s01 += __shfl_xor_sync(0xFFFFFFFF, s01, 2);
        s11 += __shfl_xor_sync(0xFFFFFFFF, s11, 1);
        s11 += __shfl_xor_sync(0xFFFFFFFF, s11, 2);
        if (tr == 0) {
            int lr0 = 2 * (rowW + tq);
            int lr1 = 2 * (rowW + tq + 8);
            s_part[lr0][warpN]     = s00;
            s_part[lr0 + 1][warpN] = s10;
            s_part[lr1][warpN]     = s01;
            s_part[lr1 + 1][warpN] = s11;
        }
        __syncthreads();
        if (tid < 128)
            g_part[(rowOff + (long)yl * 128 + tid) * 4 + blockIdx.x] =
                (s_part[tid][0] + s_part[tid][1]) + (s_part[tid][2] + s_part[tid][3]);
    }
}

// ---------------- merged final reduce: pp | ep | dp ----------------
__global__ void reduce_all_kernel(const float* __restrict__ pp_bl,
                                  const float* __restrict__ ep_bl,
                                  const float* __restrict__ dp_bl,
                                  float* __restrict__ outP,
                                  float* __restrict__ outE,
                                  float* __restrict__ outD) {
    int i = blockIdx.x * 256 + threadIdx.x;
    if (i >= TOTROWS) return;
    float s = (g_part[(long)i * 4 + 0] + g_part[(long)i * 4 + 1]) +
              (g_part[(long)i * 4 + 2] + g_part[(long)i * 4 + 3]);
    const int nPP = NB * MAXF, nPE = 2 * NB * MAXF;
    if (i < nPP)       outP[i]        = pp_bl[0] + s;
    else if (i < nPE)  outE[i - nPP]  = ep_bl[0] + s;
    else               outD[i - nPE]  = dp_bl[0] + s;
}

// ---------------- launch ----------------
extern "C" void kernel_launch(void* const* d_in, const int* in_sizes, int n_in,
                              void* d_out, int out_size) {
    const float* H     = (const float*)d_in[0];
    const int*   Dgt   = (const int*)  d_in[1];
    const float* Pgt   = (const float*)d_in[2];
    const float* Egt   = (const float*)d_in[3];
    const float* dp_w1 = (const float*)d_in[4];
    const float* dp_b1 = (const float*)d_in[5];
    const float* dp_w2 = (const float*)d_in[6];
    const float* dp_b2 = (const float*)d_in[7];
    const float* dp_wl = (const float*)d_in[8];
    const float* dp_bl = (const float*)d_in[9];
    const float* pp_w1 = (const float*)d_in[10];
    const float* pp_b1 = (const float*)d_in[11];
    const float* pp_w2 = (const float*)d_in[12];
    const float* pp_b2 = (const float*)d_in[13];
    const float* pp_wl = (const float*)d_in[14];
    const float* pp_bl = (const float*)d_in[15];
    const float* ep_w1 = (const float*)d_in[16];
    const float* ep_b1 = (const float*)d_in[17];
    const float* ep_w2 = (const float*)d_in[18];
    const float* ep_b2 = (const float*)d_in[19];
    const float* ep_wl = (const float*)d_in[20];
    const float* ep_bl = (const float*)d_in[21];
    const float* pw    = (const float*)d_in[22];
    const float* pb    = (const float*)d_in[23];
    const float* ew    = (const float*)d_in[24];
    const float* eb    = (const float*)d_in[25];

    float* out  = (float*)d_out;
    float* outH = out;                                   // (16,2048,512)
    float* outD = out + (long)NB * MAXF * DMODEL;        // (16,512)
    float* outP = outD + NB * SEQ;                       // (16,2048)
    float* outE = outP + NB * MAXF;                      // (16,2048)

    cudaFuncSetAttribute(conv_wino_kernel<1>, cudaFuncAttributeMaxDynamicSharedMemorySize, DSM_TOT);
    cudaFuncSetAttribute(conv_wino_kernel<2>, cudaFuncAttributeMaxDynamicSharedMemorySize, DSM_TOT);

    float* gHexp; cudaGetSymbolAddress((void**)&gHexp, g_Hexp);
    float* gYp;   cudaGetSymbolAddress((void**)&gYp, g_Yp);
    float* gYe;   cudaGetSymbolAddress((void**)&gYe, g_Ye);
    float* gYd;   cudaGetSymbolAddress((void**)&gYd, g_Yd);

    // 1: Winograd weight transforms
    wtrans_wino_kernel<<<6 * 512, 512>>>(dp_w1, dp_w2, pp_w1, pp_w2, ep_w1, ep_w2);
    // 2: duration indices
    duration_idx_kernel<<<NB, 512>>>(Dgt);
    // 3: expand + adapt (fp32 Hexp + outH)
    gather_adapt_kernel<<<NB * MAXF, 128>>>(H, Pgt, Egt, pw, pb, ew, eb, outH);
    // 4: input transform for layer 1: Hexp (16384 pairs) + H (4096 pairs)
    utrans_kernel<<<20480, 128>>>(gHexp, MAXF, 16384, H, SEQ, 4096, H, SEQ, 0);
    // 5: pad so ncu (-s 5 -c 1) profiles the layer-1 conv
    noop_kernel<<<1, 32>>>();
    // 6: layer-1 convs (pp + ep + dp), pure-GEMM Winograd
    conv_wino_kernel<1><<<dim3(4, 576), 512, DSM_TOT>>>(pp_b1, ep_b1, dp_b1,
                                                        nullptr, nullptr, nullptr);
    // 7: input transform for layer 2: Yp + Ye + Yd
    utrans_kernel<<<36864, 128>>>(gYp, MAXF, 16384, gYe, MAXF, 16384, gYd, SEQ, 4096);
    // 8: layer-2 convs + fused linear partials
    conv_wino_kernel<2><<<dim3(4, 576), 512, DSM_TOT>>>(pp_b2, ep_b2, dp_b2,
                                                        pp_wl, ep_wl, dp_wl);
    // 9: final reduce
    reduce_all_kernel<<<(TOTROWS + 255) / 256, 256>>>(pp_bl, ep_bl, dp_bl, outP, outE, outD);
}

// round 14
// speedup vs baseline: 1.3692x; 1.3692x over previous
#include <cuda_runtime.h>
#include <cuda_bf16.h>
#include <cstdint>

#define NB     16
#define SEQ    512
#define DMODEL 512
#define MAXF   2048

// ---------------- scratch (static __device__ arrays: allowed) ----------------
__device__ __align__(128) float g_Hexp[NB * MAXF * DMODEL];   // fp32 Hexp
__device__ __align__(128) float g_Yp  [NB * MAXF * DMODEL];   // pp layer1 out (fp32)
__device__ __align__(128) float g_Ye  [NB * MAXF * DMODEL];   // ep layer1 out
__device__ __align__(128) float g_Yd  [NB * SEQ  * DMODEL];   // dp layer1 out
// U: Winograd input tiles, PRE-SWIZZLED smem image:
//   [block(64 pairs)][chunk(32 x 16ch)][pt(4)][hl(2)][64pr x 16ch swizzled 2KB]
#define UBLK_B   524288L                 // 32 chunks x 16KB
__device__ __align__(128) uint8_t g_U[576 * UBLK_B];          // 302 MB
// V: Winograd weight tiles, PRE-SWIZZLED: [conv][xblk][chunk][pt][hl][128f x 16ch swizzled 4KB]
__device__ __align__(128) uint8_t g_V[6L * 4 * 32 * 32768];   // 25 MB
#define TOTROWS (2 * NB * MAXF + NB * SEQ)   // pp | ep | dp output rows
__device__ float g_part[TOTROWS * 4];
__device__ int   g_idx [NB * MAXF];

// ================= baseline-ISA helpers (compute_103-safe) =================
__device__ __forceinline__ uint32_t smem_to_u32(const void* p) {
    uint32_t a;
    asm("{ .reg .u64 t; cvta.to.shared.u64 t, %1; cvt.u32.u64 %0, t; }" : "=r"(a) : "l"(p));
    return a;
}
__device__ __forceinline__ void cpasync16(uint32_t dst, const void* src) {
    asm volatile("cp.async.cg.shared.global [%0], [%1], 16;" :: "r"(dst), "l"(src));
}
#define CP_COMMIT() asm volatile("cp.async.commit_group;" ::: "memory")
#define CP_WAIT1()  asm volatile("cp.async.wait_group 1;"  ::: "memory")

__device__ __forceinline__ void ldmx4(uint32_t* r, uint32_t addr) {
    asm volatile("ldmatrix.sync.aligned.m8n8.x4.shared.b16 {%0,%1,%2,%3}, [%4];"
                 : "=r"(r[0]), "=r"(r[1]), "=r"(r[2]), "=r"(r[3]) : "r"(addr));
}
__device__ __forceinline__ void mma16816(float* d, const uint32_t* a, const uint32_t* b) {
    asm volatile("mma.sync.aligned.m16n8k16.row.col.f32.bf16.bf16.f32 "
                 "{%0,%1,%2,%3}, {%4,%5,%6,%7}, {%8,%9}, {%0,%1,%2,%3};"
                 : "+f"(d[0]), "+f"(d[1]), "+f"(d[2]), "+f"(d[3])
                 : "r"(a[0]), "r"(a[1]), "r"(a[2]), "r"(a[3]), "r"(b[0]), "r"(b[1]));
}
__device__ __forceinline__ uint32_t pack2bf(float a, float b) {
    __nv_bfloat162 t = __floats2bfloat162_rn(a, b);
    return *reinterpret_cast<uint32_t*>(&t);
}
// packed tile addr: 4 rows per 128B line (row = 16ch bf16 = 2 x 16B segs), XOR swizzle
#define TADDR16(r, s) ((uint32_t)((((r) >> 2) * 128) + ((((((r) & 3) << 1) | (s)) ^ (((r) >> 2) & 7)) << 4)))

// ---------------- prep: duration scan (blocks 0..15) + Winograd weight transform ----------------
__global__ void prep_kernel(const int* __restrict__ Dgt,
                            const float* __restrict__ w0p, const float* __restrict__ w1p,
                            const float* __restrict__ w2p, const float* __restrict__ w3p,
                            const float* __restrict__ w4p, const float* __restrict__ w5p) {
    const int tid = threadIdx.x;
    if (blockIdx.x < 16) {
        // ---- duration cumsum + searchsorted ----
        __shared__ int cs[512];
        int b = blockIdx.x;
        int v = Dgt[b * 512 + tid];
        cs[tid] = v > 0 ? v : 0;
        __syncthreads();
        for (int off = 1; off < 512; off <<= 1) {
            int add = (tid >= off) ? cs[tid - off] : 0;
            __syncthreads();
            cs[tid] += add;
            __syncthreads();
        }
        int total = cs[511];
        int Tmax  = total < MAXF ? total : MAXF;
        for (int t = tid; t < MAXF; t += 512) {
            int r;
            if (t >= Tmax) {
                r = -1;
            } else {
                int lo = 0, hi = 511;
                while (lo < hi) {
                    int mid = (lo + hi) >> 1;
                    if (cs[mid] > t) hi = mid; else lo = mid + 1;
                }
                r = lo;
            }
            g_idx[b * MAXF + t] = r;
        }
        return;
    }
    // ---- weight transform: one block per (conv, xblk, chunk) ----
    int q = blockIdx.x - 16;          // 0..767
    int conv  = q >> 7;
    int xblk  = (q >> 5) & 3;
    int chunk = q & 31;
    const float* w = conv == 0 ? w0p : conv == 1 ? w1p : conv == 2 ? w2p :
                     conv == 3 ? w3p : conv == 4 ? w4p : w5p;
    int f_loc = tid >> 2, qq = tid & 3;
    int f = xblk * 128 + f_loc;
    int c = chunk * 16 + qq * 4;
    float V[4][4];                    // [pt][ch]
#pragma unroll
    for (int k = 0; k < 4; k++) {
        const float* wp = w + ((long)f * 512 + c + k) * 3;
        float w0 = wp[0], w1 = wp[1], w2 = wp[2];
        V[0][k] = w0;
        V[1][k] = 0.5f * (w0 + w1 + w2);
        V[2][k] = 0.5f * (w0 - w1 + w2);
        V[3][k] = w2;
    }
    uint8_t* dst = g_V + ((long)(conv * 4 + xblk) * 32 + chunk) * 32768;
    const uint32_t base = TADDR16(f_loc, qq >> 1) + (qq & 1) * 8;
#pragma unroll
    for (int pt = 0; pt < 4; pt++) {
        float h[4], l[4];
#pragma unroll
        for (int k = 0; k < 4; k++) {
            __nv_bfloat16 hb = __float2bfloat16(V[pt][k]);
            h[k] = __bfloat162float(hb);
            l[k] = V[pt][k] - h[k];
        }
        uint2 hv = make_uint2(pack2bf(h[0], h[1]), pack2bf(h[2], h[3]));
        uint2 lv = make_uint2(pack2bf(l[0], l[1]), pack2bf(l[2], l[3]));
        *(uint2*)(dst + pt * 8192 + base)        = hv;
        *(uint2*)(dst + pt * 8192 + 4096 + base) = lv;
    }
}

// ---------------- gather H_exp (fp32) + fused variance adapt ----------------
__global__ void gather_adapt_kernel(const float* __restrict__ H,
                                    const float* __restrict__ P,
                                    const float* __restrict__ E,
                                    const float* __restrict__ pw,
                                    const float* __restrict__ pb,
                                    const float* __restrict__ ew,
                                    const float* __restrict__ eb,
                                    float* __restrict__ outH) {
    int bt  = blockIdx.x;
    int b   = bt >> 11;
    int idx = g_idx[bt];
    int d   = threadIdx.x * 4;
    float4 h = make_float4(0.f, 0.f, 0.f, 0.f);
    if (idx >= 0) h = *(const float4*)&H[((long)(b * 512 + idx)) * 512 + d];
    long xo = (long)bt * 512 + d;
    *(float4*)&g_Hexp[xo] = h;

    float p = P[bt], e = E[bt];
    float4 pw4 = *(const float4*)&pw[d];
    float4 pb4 = *(const float4*)&pb[d];
    float4 ew4 = *(const float4*)&ew[d];
    float4 eb4 = *(const float4*)&eb[d];
    float4 o;
    o.x = h.x + p * pw4.x + pb4.x + e * ew4.x + eb4.x;
    o.y = h.y + p * pw4.y + pb4.y + e * ew4.y + eb4.y;
    o.z = h.z + p * pw4.z + pb4.z + e * ew4.z + eb4.z;
    o.w = h.w + p * pw4.w + pb4.w + e * ew4.w + eb4.w;
    *(float4*)&outH[xo] = o;
}

// ---------------- Winograd input transform -> pre-swizzled U blocks ----------------
// One block = 64 output pairs (one conv y-tile), 512 threads (64 pr x 8 cg of 2ch).
// Writes the exact smem image: [chunk][pt][hl][2KB swizzled]. Warp-coalesced 128B lines.
__global__ void utrans_kernel(const float* __restrict__ A0, int S0, int n0,
                              const float* __restrict__ A1, int S1, int n1,
                              const float* __restrict__ A2, int S2, int n2) {
    int blk = blockIdx.x;
    const float* X; int S, loc;
    if (blk < n0)           { X = A0; S = S0; loc = blk; }
    else if (blk < n0 + n1) { X = A1; S = S1; loc = blk - n0; }
    else                    { X = A2; S = S2; loc = blk - n0 - n1; }
    const int ppb = S >> 1;                    // pairs per batch (64 divides it)
    const int pl  = loc * 64;                  // pair index within source
    const int b   = pl / ppb;
    const int p   = (pl - b * ppb) + (threadIdx.x >> 3);   // pair within batch
    const int cg  = threadIdx.x & 7;           // 2-ch group within 16-ch chunk
    const float* Xb = X + (long)b * S * 512 + cg * 2;

    const float* rp[4];
    bool av[4];
#pragma unroll
    for (int k = 0; k < 4; k++) {
        int s = 2 * p - 1 + k;
        av[k] = (s >= 0 && s < S);
        rp[k] = Xb + (long)(av[k] ? s : 0) * 512;
    }
    uint8_t* dstblk = g_U + (long)blk * UBLK_B;
    const uint32_t base = TADDR16(threadIdx.x >> 3, cg >> 2) + (cg & 3) * 4;

    for (int ch = 0; ch < 32; ch++) {
        float2 d[4];
#pragma unroll
        for (int k = 0; k < 4; k++)
            d[k] = av[k] ? *(const float2*)(rp[k] + ch * 16) : make_float2(0.f, 0.f);
        float U[4][2];
        U[0][0] = d[0].x - d[2].x;  U[0][1] = d[0].y - d[2].y;
        U[1][0] = d[1].x + d[2].x;  U[1][1] = d[1].y + d[2].y;
        U[2][0] = d[2].x - d[1].x;  U[2][1] = d[2].y - d[1].y;
        U[3][0] = d[1].x - d[3].x;  U[3][1] = d[1].y - d[3].y;
        uint8_t* dc = dstblk + (long)ch * 16384;
#pragma unroll
        for (int pt = 0; pt < 4; pt++) {
            __nv_bfloat16 h0 = __float2bfloat16(U[pt][0]);
            __nv_bfloat16 h1 = __float2bfloat16(U[pt][1]);
            float l0 = U[pt][0] - __bfloat162float(h0);
            float l1 = U[pt][1] - __bfloat162float(h1);
            __nv_bfloat162 hp = __halves2bfloat162(h0, h1);
            *(uint32_t*)(dc + pt * 4096 + base)        = *(uint32_t*)&hp;
            *(uint32_t*)(dc + pt * 4096 + 2048 + base) = pack2bf(l0, l1);
        }
    }
}

// ---------------- Winograd F(2,3) conv: flat-copy staging + pure-GEMM mainloop ----------------
// Merged pp+ep+dp. Grid (4, 576): y<256 pp, <512 ep, else dp.
// CTA: 64 pairs x 128 filters, 512 threads (16 warps 4M x 4N, warp 16pr x 32f).
// 32 iters of 16-ch chunks; A (16KB) and B (32KB) staged as SEQUENTIAL flat copies
// from pre-swizzled gmem blocks. Ring-3 both, one barrier/iter.
#define A_BUF   16384
#define B_BASE  49152
#define B_SLOT  32768
#define DSM_TOT (B_BASE + 3 * B_SLOT)   // 147456

template <int LAYER>
__global__ __launch_bounds__(512, 1)
void conv_wino_kernel(const float* __restrict__ b_pp, const float* __restrict__ b_ep,
                      const float* __restrict__ b_dp, const float* __restrict__ wl_pp,
                      const float* __restrict__ wl_ep, const float* __restrict__ wl_dp) {
    extern __shared__ char sm[];
    const uint32_t sb = smem_to_u32(sm);
    __shared__ float s_bias[128];
    __shared__ float s_wl[128];
    __shared__ float s_part[128][4];

    const int tid  = threadIdx.x;
    const int lane = tid & 31;
    const int wid  = tid >> 5;
    const int warpM = wid & 3, warpN = wid >> 2;
    const int rowW = warpM * 16;
    const int colW = warpN * 32;

    // ---- job decode ----
    const int y = blockIdx.y;
    int job, yl;
    if (y < 256)      { job = 0; yl = y; }
    else if (y < 512) { job = 1; yl = y - 256; }
    else              { job = 2; yl = y - 512; }
    int conv, ublk;
    if (LAYER == 1) {
        conv = job == 0 ? 2 : job == 1 ? 4 : 0;
        ublk = (job == 2) ? 256 + yl : yl;          // pp/ep share Hexp U blocks
    } else {
        conv = job == 0 ? 3 : job == 1 ? 5 : 1;
        ublk = job * 256 + yl;                      // job==2 -> 512+yl
    }
    const float* bias = job == 0 ? b_pp : job == 1 ? b_ep : b_dp;
    const float* wl   = job == 0 ? wl_pp : job == 1 ? wl_ep : wl_dp;
    float* Yout = job == 0 ? g_Yp : job == 1 ? g_Ye : g_Yd;
    const long rowOff = job == 0 ? 0 : job == 1 ? (long)NB * MAXF : 2L * NB * MAXF;

    const uint8_t* Ublk  = g_U + (long)ublk * UBLK_B;
    const uint8_t* Vbase = g_V + ((long)(conv * 4 + blockIdx.x) * 32) * 32768;

    if (tid < 128) {
        s_bias[tid] = bias[blockIdx.x * 128 + tid];
        if (LAYER == 2) s_wl[tid] = wl[blockIdx.x * 128 + tid];
    }

    // ---- flat-copy staging (fully coalesced sequential) ----
    auto stageA = [&](int it) {
        const uint32_t abuf = sb + (it % 3) * A_BUF;
        const uint8_t* src = Ublk + (long)it * 16384;
#pragma unroll
        for (int qd = 0; qd < 2; qd++) {
            int j = tid + qd * 512;
            cpasync16(abuf + j * 16, src + j * 16);
        }
    };
    auto stageB = [&](int it) {
        const uint32_t bbuf = sb + B_BASE + (it % 3) * B_SLOT;
        const uint8_t* src = Vbase + (long)it * 32768;
#pragma unroll
        for (int qd = 0; qd < 4; qd++) {
            int j = tid + qd * 512;
            cpasync16(bbuf + j * 16, src + j * 16);
        }
    };

    // ---- per-lane ldmatrix bases ----
    const int q = lane >> 3;
    const int am = rowW + ((q & 1) << 3) + (lane & 7);
    const int ac16b = q >> 1;
    int an[2];
#pragma unroll
    for (int np = 0; np < 2; np++) an[np] = colW + np * 16 + ((q >> 1) << 3) + (lane & 7);
    const int bc16b = q & 1;
    const uint32_t aOff = TADDR16(am, ac16b);
    uint32_t bOff[2];
#pragma unroll
    for (int np = 0; np < 2; np++) bOff[np] = TADDR16(an[np], bc16b);

    float acc[4][4][4];                 // [point][ntile][frag]
#pragma unroll
    for (int pt = 0; pt < 4; pt++)
#pragma unroll
        for (int nt = 0; nt < 4; nt++)
#pragma unroll
            for (int v = 0; v < 4; v++) acc[pt][nt][v] = 0.f;

    stageA(0); stageB(0); CP_COMMIT();
    stageA(1); stageB(1); CP_COMMIT();

    for (int it = 0; it < 32; it++) {
        CP_WAIT1();
        __syncthreads();
        const uint32_t aBuf = sb + (it % 3) * A_BUF;
        const uint32_t bBuf = sb + B_BASE + (it % 3) * B_SLOT;

#pragma unroll
        for (int pt = 0; pt < 4; pt++) {
            uint32_t ah[4], al[4];
            ldmx4(ah, aBuf + pt * 4096 + aOff);
            ldmx4(al, aBuf + pt * 4096 + 2048 + aOff);
            uint32_t bh[4][2], bl[4][2];
#pragma unroll
            for (int np = 0; np < 2; np++) {
                uint32_t t[4];
                ldmx4(t, bBuf + pt * 8192 + bOff[np]);
                bh[2 * np][0] = t[0]; bh[2 * np][1] = t[1];
                bh[2 * np + 1][0] = t[2]; bh[2 * np + 1][1] = t[3];
                ldmx4(t, bBuf + pt * 8192 + 4096 + bOff[np]);
                bl[2 * np][0] = t[0]; bl[2 * np][1] = t[1];
                bl[2 * np + 1][0] = t[2]; bl[2 * np + 1][1] = t[3];
            }
#pragma unroll
            for (int nt = 0; nt < 4; nt++) mma16816(acc[pt][nt], ah, bh[nt]);
#pragma unroll
            for (int nt = 0; nt < 4; nt++) mma16816(acc[pt][nt], ah, bl[nt]);
#pragma unroll
            for (int nt = 0; nt < 4; nt++) mma16816(acc[pt][nt], al, bh[nt]);
        }

        if (it + 2 < 32) { stageA(it + 2); stageB(it + 2); }
        CP_COMMIT();
    }

    // ---------------- epilogue: output transform + bias + relu ----------------
    const int tq = lane >> 2;
    const int tr = lane & 3;
    const int fBase = blockIdx.x * 128;
    if (LAYER == 1) {
#pragma unroll
        for (int nt = 0; nt < 4; nt++) {
            const int cl = colW + nt * 8 + 2 * tr;
            const float b0 = s_bias[cl], b1 = s_bias[cl + 1];
#pragma unroll
            for (int h = 0; h < 2; h++) {
                const long P = (long)yl * 64 + rowW + tq + 8 * h;
                const int v0 = 2 * h, v1 = 2 * h + 1;
                float m0a = acc[0][nt][v0], m1a = acc[1][nt][v0],
                      m2a = acc[2][nt][v0], m3a = acc[3][nt][v0];
                float m0b = acc[0][nt][v1], m1b = acc[1][nt][v1],
                      m2b = acc[2][nt][v1], m3b = acc[3][nt][v1];
                float y0a = fmaxf(m0a + m1a + m2a + b0, 0.f);
                float y0b = fmaxf(m0b + m1b + m2b + b1, 0.f);
                float y1a = fmaxf(m1a - m2a - m3a + b0, 0.f);
                float y1b = fmaxf(m1b - m2b - m3b + b1, 0.f);
                *(float2*)&Yout[(2 * P)     * 512 + fBase + cl] = make_float2(y0a, y0b);
                *(float2*)&Yout[(2 * P + 1) * 512 + fBase + cl] = make_float2(y1a, y1b);
            }
        }
    } else {
        float s00 = 0.f, s10 = 0.f, s01 = 0.f, s11 = 0.f;
#pragma unroll
        for (int nt = 0; nt < 4; nt++) {
            const int cl = colW + nt * 8 + 2 * tr;
            const float b0 = s_bias[cl], b1 = s_bias[cl + 1];
            const float w0 = s_wl[cl], w1 = s_wl[cl + 1];
#pragma unroll
            for (int h = 0; h < 2; h++) {
                const int v0 = 2 * h, v1 = 2 * h + 1;
                float m0a = acc[0][nt][v0], m1a = acc[1][nt][v0],
                      m2a = acc[2][nt][v0], m3a = acc[3][nt][v0];
                float m0b = acc[0][nt][v1], m1b = acc[1][nt][v1],
                      m2b = acc[2][nt][v1], m3b = acc[3][nt][v1];
                float sy0 = fmaxf(m0a + m1a + m2a + b0, 0.f) * w0
                          + fmaxf(m0b + m1b + m2b + b1, 0.f) * w1;
                float sy1 = fmaxf(m1a - m2a - m3a + b0, 0.f) * w0
                          + fmaxf(m1b - m2b - m3b + b1, 0.f) * w1;
                if (h == 0) { s00 += sy0; s10 += sy1; }
                else        { s01 += sy0; s11 += sy1; }
            }
        }
        s00 += __shfl_xor_sync(0xFFFFFFFF, s00, 1);
        s00 += __shfl_xor_sync(0xFFFFFFFF, s00, 2);
        s10 += __shfl_xor_sync(0xFFFFFFFF, s10, 1);
        s10 += __shfl_xor_sync(0xFFFFFFFF, s10, 2);
        s01 += __shfl_xor_sync(0xFFFFFFFF, s01, 1);
        s01 += __shfl_xor_sync(0xFFFFFFFF, s01, 2);
        s11 += __shfl_xor_sync(0xFFFFFFFF, s11, 1);
        s11 += __shfl_xor_sync(0xFFFFFFFF, s11, 2);
        if (tr == 0) {
            int lr0 = 2 * (rowW + tq);
            int lr1 = 2 * (rowW + tq + 8);
            s_part[lr0][warpN]     = s00;
            s_part[lr0 + 1][warpN] = s10;
            s_part[lr1][warpN]     = s01;
            s_part[lr1 + 1][warpN] = s11;
        }
        __syncthreads();
        if (tid < 128)
            g_part[(rowOff + (long)yl * 128 + tid) * 4 + blockIdx.x] =
                (s_part[tid][0] + s_part[tid][1]) + (s_part[tid][2] + s_part[tid][3]);
    }
}

// ---------------- merged final reduce: pp | ep | dp ----------------
__global__ void reduce_all_kernel(const float* __restrict__ pp_bl,
                                  const float* __restrict__ ep_bl,
                                  const float* __restrict__ dp_bl,
                                  float* __restrict__ outP,
                                  float* __restrict__ outE,
                                  float* __restrict__ outD) {
    int i = blockIdx.x * 256 + threadIdx.x;
    if (i >= TOTROWS) return;
    float s = (g_part[(long)i * 4 + 0] + g_part[(long)i * 4 + 1]) +
              (g_part[(long)i * 4 + 2] + g_part[(long)i * 4 + 3]);
    const int nPP = NB * MAXF, nPE = 2 * NB * MAXF;
    if (i < nPP)       outP[i]        = pp_bl[0] + s;
    else if (i < nPE)  outE[i - nPP]  = ep_bl[0] + s;
    else               outD[i - nPE]  = dp_bl[0] + s;
}

// ---------------- launch ----------------
extern "C" void kernel_launch(void* const* d_in, const int* in_sizes, int n_in,
                              void* d_out, int out_size) {
    const float* H     = (const float*)d_in[0];
    const int*   Dgt   = (const int*)  d_in[1];
    const float* Pgt   = (const float*)d_in[2];
    const float* Egt   = (const float*)d_in[3];
    const float* dp_w1 = (const float*)d_in[4];
    const float* dp_b1 = (const float*)d_in[5];
    const float* dp_w2 = (const float*)d_in[6];
    const float* dp_b2 = (const float*)d_in[7];
    const float* dp_wl = (const float*)d_in[8];
    const float* dp_bl = (const float*)d_in[9];
    const float* pp_w1 = (const float*)d_in[10];
    const float* pp_b1 = (const float*)d_in[11];
    const float* pp_w2 = (const float*)d_in[12];
    const float* pp_b2 = (const float*)d_in[13];
    const float* pp_wl = (const float*)d_in[14];
    const float* pp_bl = (const float*)d_in[15];
    const float* ep_w1 = (const float*)d_in[16];
    const float* ep_b1 = (const float*)d_in[17];
    const float* ep_w2 = (const float*)d_in[18];
    const float* ep_b2 = (const float*)d_in[19];
    const float* ep_wl = (const float*)d_in[20];
    const float* ep_bl = (const float*)d_in[21];
    const float* pw    = (const float*)d_in[22];
    const float* pb    = (const float*)d_in[23];
    const float* ew    = (const float*)d_in[24];
    const float* eb    = (const float*)d_in[25];

    float* out  = (float*)d_out;
    float* outH = out;                                   // (16,2048,512)
    float* outD = out + (long)NB * MAXF * DMODEL;        // (16,512)
    float* outP = outD + NB * SEQ;                       // (16,2048)
    float* outE = outP + NB * MAXF;                      // (16,2048)

    cudaFuncSetAttribute(conv_wino_kernel<1>, cudaFuncAttributeMaxDynamicSharedMemorySize, DSM_TOT);
    cudaFuncSetAttribute(conv_wino_kernel<2>, cudaFuncAttributeMaxDynamicSharedMemorySize, DSM_TOT);

    float* gHexp; cudaGetSymbolAddress((void**)&gHexp, g_Hexp);
    float* gYp;   cudaGetSymbolAddress((void**)&gYp, g_Yp);
    float* gYe;   cudaGetSymbolAddress((void**)&gYe, g_Ye);
    float* gYd;   cudaGetSymbolAddress((void**)&gYd, g_Yd);

    // 1: duration scan + Winograd weight transforms (merged)
    prep_kernel<<<16 + 768, 512>>>(Dgt, dp_w1, dp_w2, pp_w1, pp_w2, ep_w1, ep_w2);
    // 2: expand + adapt (fp32 Hexp + outH)
    gather_adapt_kernel<<<NB * MAXF, 128>>>(H, Pgt, Egt, pw, pb, ew, eb, outH);
    // 3: input transform layer 1: Hexp (U blocks 0..255) + H (256..319)
    utrans_kernel<<<320, 512>>>(gHexp, MAXF, 256, H, SEQ, 64, H, SEQ, 0);
    // 4: layer-1 convs (pp + ep + dp)  ← profiled slot
    conv_wino_kernel<1><<<dim3(4, 576), 512, DSM_TOT>>>(pp_b1, ep_b1, dp_b1,
                                                        nullptr, nullptr, nullptr);
    // 5: input transform layer 2: Yp (0..255) + Ye (256..511) + Yd (512..575)
    utrans_kernel<<<576, 512>>>(gYp, MAXF, 256, gYe, MAXF, 256, gYd, SEQ, 64);
    // 6: layer-2 convs + fused linear partials
    conv_wino_kernel<2><<<dim3(4, 576), 512, DSM_TOT>>>(pp_b2, ep_b2, dp_b2,
                                                        pp_wl, ep_wl, dp_wl);
    // 7: final reduce
    reduce_all_kernel<<<(TOTROWS + 255) / 256, 256>>>(pp_bl, ep_bl, dp_bl, outP, outE, outD);
}

// round 16
// speedup vs baseline: 1.4742x; 1.0766x over previous
#include <cuda_runtime.h>
#include <cuda_bf16.h>
#include <cstdint>

#define NB     16
#define SEQ    512
#define DMODEL 512
#define MAXF   2048

// ---------------- scratch (static __device__ arrays: allowed) ----------------
__device__ __align__(128) float g_Hexp[NB * MAXF * DMODEL];   // fp32 Hexp
__device__ __align__(128) float g_Yp  [NB * MAXF * DMODEL];   // pp layer1 out (fp32)
__device__ __align__(128) float g_Ye  [NB * MAXF * DMODEL];   // ep layer1 out
__device__ __align__(128) float g_Yd  [NB * SEQ  * DMODEL];   // dp layer1 out
// U: Winograd input tiles, PRE-SWIZZLED smem image:
//   [block(64 pairs)][chunk(32 x 16ch)][pt(4)][hl(2)][64pr x 16ch swizzled 2KB]
#define UBLK_B   524288L                 // 32 chunks x 16KB
__device__ __align__(128) uint8_t g_U[576 * UBLK_B];          // 302 MB
// V: Winograd weight tiles, PRE-SWIZZLED: [conv][xblk][chunk][pt][hl][128f x 16ch swizzled 4KB]
__device__ __align__(128) uint8_t g_V[6L * 4 * 32 * 32768];   // 25 MB
#define TOTROWS (2 * NB * MAXF + NB * SEQ)   // pp | ep | dp output rows
__device__ float g_part[TOTROWS * 4];
__device__ int   g_idx [NB * MAXF];

// ================= baseline-ISA helpers (compute_103-safe) =================
__device__ __forceinline__ uint32_t smem_to_u32(const void* p) {
    uint32_t a;
    asm("{ .reg .u64 t; cvta.to.shared.u64 t, %1; cvt.u32.u64 %0, t; }" : "=r"(a) : "l"(p));
    return a;
}
__device__ __forceinline__ void cpasync16(uint32_t dst, const void* src) {
    asm volatile("cp.async.cg.shared.global [%0], [%1], 16;" :: "r"(dst), "l"(src));
}
#define CP_COMMIT() asm volatile("cp.async.commit_group;" ::: "memory")
#define CP_WAIT1()  asm volatile("cp.async.wait_group 1;"  ::: "memory")

__device__ __forceinline__ void ldmx4(uint32_t* r, uint32_t addr) {
    asm volatile("ldmatrix.sync.aligned.m8n8.x4.shared.b16 {%0,%1,%2,%3}, [%4];"
                 : "=r"(r[0]), "=r"(r[1]), "=r"(r[2]), "=r"(r[3]) : "r"(addr));
}
__device__ __forceinline__ void mma16816(float* d, const uint32_t* a, const uint32_t* b) {
    asm volatile("mma.sync.aligned.m16n8k16.row.col.f32.bf16.bf16.f32 "
                 "{%0,%1,%2,%3}, {%4,%5,%6,%7}, {%8,%9}, {%0,%1,%2,%3};"
                 : "+f"(d[0]), "+f"(d[1]), "+f"(d[2]), "+f"(d[3])
                 : "r"(a[0]), "r"(a[1]), "r"(a[2]), "r"(a[3]), "r"(b[0]), "r"(b[1]));
}
__device__ __forceinline__ uint32_t pack2bf(float a, float b) {
    __nv_bfloat162 t = __floats2bfloat162_rn(a, b);
    return *reinterpret_cast<uint32_t*>(&t);
}
// packed tile addr: 4 rows per 128B line (row = 16ch bf16 = 2 x 16B segs), XOR swizzle
#define TADDR16(r, s) ((uint32_t)((((r) >> 2) * 128) + ((((((r) & 3) << 1) | (s)) ^ (((r) >> 2) & 7)) << 4)))

// ---------------- prep: duration scan (blocks 0..15) + Winograd weight transform ----------------
__global__ void prep_kernel(const int* __restrict__ Dgt,
                            const float* __restrict__ w0p, const float* __restrict__ w1p,
                            const float* __restrict__ w2p, const float* __restrict__ w3p,
                            const float* __restrict__ w4p, const float* __restrict__ w5p) {
    const int tid = threadIdx.x;
    if (blockIdx.x < 16) {
        __shared__ int cs[512];
        int b = blockIdx.x;
        int v = Dgt[b * 512 + tid];
        cs[tid] = v > 0 ? v : 0;
        __syncthreads();
        for (int off = 1; off < 512; off <<= 1) {
            int add = (tid >= off) ? cs[tid - off] : 0;
            __syncthreads();
            cs[tid] += add;
            __syncthreads();
        }
        int total = cs[511];
        int Tmax  = total < MAXF ? total : MAXF;
        for (int t = tid; t < MAXF; t += 512) {
            int r;
            if (t >= Tmax) {
                r = -1;
            } else {
                int lo = 0, hi = 511;
                while (lo < hi) {
                    int mid = (lo + hi) >> 1;
                    if (cs[mid] > t) hi = mid; else lo = mid + 1;
                }
                r = lo;
            }
            g_idx[b * MAXF + t] = r;
        }
        return;
    }
    int q = blockIdx.x - 16;          // 0..767
    int conv  = q >> 7;
    int xblk  = (q >> 5) & 3;
    int chunk = q & 31;
    const float* w = conv == 0 ? w0p : conv == 1 ? w1p : conv == 2 ? w2p :
                     conv == 3 ? w3p : conv == 4 ? w4p : w5p;
    int f_loc = tid >> 2, qq = tid & 3;
    int f = xblk * 128 + f_loc;
    int c = chunk * 16 + qq * 4;
    float V[4][4];
#pragma unroll
    for (int k = 0; k < 4; k++) {
        const float* wp = w + ((long)f * 512 + c + k) * 3;
        float w0 = wp[0], w1 = wp[1], w2 = wp[2];
        V[0][k] = w0;
        V[1][k] = 0.5f * (w0 + w1 + w2);
        V[2][k] = 0.5f * (w0 - w1 + w2);
        V[3][k] = w2;
    }
    uint8_t* dst = g_V + ((long)(conv * 4 + xblk) * 32 + chunk) * 32768;
    const uint32_t base = TADDR16(f_loc, qq >> 1) + (qq & 1) * 8;
#pragma unroll
    for (int pt = 0; pt < 4; pt++) {
        float h[4], l[4];
#pragma unroll
        for (int k = 0; k < 4; k++) {
            __nv_bfloat16 hb = __float2bfloat16(V[pt][k]);
            h[k] = __bfloat162float(hb);
            l[k] = V[pt][k] - h[k];
        }
        uint2 hv = make_uint2(pack2bf(h[0], h[1]), pack2bf(h[2], h[3]));
        uint2 lv = make_uint2(pack2bf(l[0], l[1]), pack2bf(l[2], l[3]));
        *(uint2*)(dst + pt * 8192 + base)        = hv;
        *(uint2*)(dst + pt * 8192 + 4096 + base) = lv;
    }
}

// ---------------- gather H_exp (fp32) + fused variance adapt ----------------
__global__ void gather_adapt_kernel(const float* __restrict__ H,
                                    const float* __restrict__ P,
                                    const float* __restrict__ E,
                                    const float* __restrict__ pw,
                                    const float* __restrict__ pb,
                                    const float* __restrict__ ew,
                                    const float* __restrict__ eb,
                                    float* __restrict__ outH) {
    int bt  = blockIdx.x;
    int b   = bt >> 11;
    int idx = g_idx[bt];
    int d   = threadIdx.x * 4;
    float4 h = make_float4(0.f, 0.f, 0.f, 0.f);
    if (idx >= 0) h = *(const float4*)&H[((long)(b * 512 + idx)) * 512 + d];
    long xo = (long)bt * 512 + d;
    *(float4*)&g_Hexp[xo] = h;

    float p = P[bt], e = E[bt];
    float4 pw4 = *(const float4*)&pw[d];
    float4 pb4 = *(const float4*)&pb[d];
    float4 ew4 = *(const float4*)&ew[d];
    float4 eb4 = *(const float4*)&eb[d];
    float4 o;
    o.x = h.x + p * pw4.x + pb4.x + e * ew4.x + eb4.x;
    o.y = h.y + p * pw4.y + pb4.y + e * ew4.y + eb4.y;
    o.z = h.z + p * pw4.z + pb4.z + e * ew4.z + eb4.z;
    o.w = h.w + p * pw4.w + pb4.w + e * ew4.w + eb4.w;
    *(float4*)&outH[xo] = o;
}

// ---------------- Winograd input transform -> pre-swizzled U blocks ----------------
__global__ void utrans_kernel(const float* __restrict__ A0, int S0, int n0,
                              const float* __restrict__ A1, int S1, int n1,
                              const float* __restrict__ A2, int S2, int n2) {
    int blk = blockIdx.x;
    const float* X; int S, loc;
    if (blk < n0)           { X = A0; S = S0; loc = blk; }
    else if (blk < n0 + n1) { X = A1; S = S1; loc = blk - n0; }
    else                    { X = A2; S = S2; loc = blk - n0 - n1; }
    const int ppb = S >> 1;
    const int pl  = loc * 64;
    const int b   = pl / ppb;
    const int p   = (pl - b * ppb) + (threadIdx.x >> 3);
    const int cg  = threadIdx.x & 7;
    const float* Xb = X + (long)b * S * 512 + cg * 2;

    const float* rp[4];
    bool av[4];
#pragma unroll
    for (int k = 0; k < 4; k++) {
        int s = 2 * p - 1 + k;
        av[k] = (s >= 0 && s < S);
        rp[k] = Xb + (long)(av[k] ? s : 0) * 512;
    }
    uint8_t* dstblk = g_U + (long)blk * UBLK_B;
    const uint32_t base = TADDR16(threadIdx.x >> 3, cg >> 2) + (cg & 3) * 4;

    for (int ch = 0; ch < 32; ch++) {
        float2 d[4];
#pragma unroll
        for (int k = 0; k < 4; k++)
            d[k] = av[k] ? *(const float2*)(rp[k] + ch * 16) : make_float2(0.f, 0.f);
        float U[4][2];
        U[0][0] = d[0].x - d[2].x;  U[0][1] = d[0].y - d[2].y;
        U[1][0] = d[1].x + d[2].x;  U[1][1] = d[1].y + d[2].y;
        U[2][0] = d[2].x - d[1].x;  U[2][1] = d[2].y - d[1].y;
        U[3][0] = d[1].x - d[3].x;  U[3][1] = d[1].y - d[3].y;
        uint8_t* dc = dstblk + (long)ch * 16384;
#pragma unroll
        for (int pt = 0; pt < 4; pt++) {
            __nv_bfloat16 h0 = __float2bfloat16(U[pt][0]);
            __nv_bfloat16 h1 = __float2bfloat16(U[pt][1]);
            float l0 = U[pt][0] - __bfloat162float(h0);
            float l1 = U[pt][1] - __bfloat162float(h1);
            __nv_bfloat162 hp = __halves2bfloat162(h0, h1);
            *(uint32_t*)(dc + pt * 4096 + base)        = *(uint32_t*)&hp;
            *(uint32_t*)(dc + pt * 4096 + 2048 + base) = pack2bf(l0, l1);
        }
    }
}

// ---------------- Winograd F(2,3) conv: fat 32x32 warp tiles (8 warps, 256 thr) ----------------
// Merged pp+ep+dp. Grid (4, 576). CTA: 64 pairs x 128 filters, 256 threads
// (8 warps 2M x 4N, warp 32pr x 32f, acc[pt][mt][nt][4] = 128 fp32).
// LDSM:MMA per pt = 8:24 (was 6:12) -> per-SM LDSM wavefronts cut 33%.
#define A_BUF   16384
#define B_BASE  49152
#define B_SLOT  32768
#define DSM_TOT (B_BASE + 3 * B_SLOT)   // 147456

template <int LAYER>
__global__ __launch_bounds__(256, 1)
void conv_wino_kernel(const float* __restrict__ b_pp, const float* __restrict__ b_ep,
                      const float* __restrict__ b_dp, const float* __restrict__ wl_pp,
                      const float* __restrict__ wl_ep, const float* __restrict__ wl_dp) {
    extern __shared__ char sm[];
    const uint32_t sb = smem_to_u32(sm);
    __shared__ float s_bias[128];
    __shared__ float s_wl[128];
    __shared__ float s_part[128][4];

    const int tid  = threadIdx.x;
    const int lane = tid & 31;
    const int wid  = tid >> 5;
    const int warpM = wid & 1, warpN = wid >> 1;   // 2M x 4N
    const int rowW = warpM * 32;                   // 32 pairs per warp
    const int colW = warpN * 32;                   // 32 filters per warp

    // ---- job decode ----
    const int y = blockIdx.y;
    int job, yl;
    if (y < 256)      { job = 0; yl = y; }
    else if (y < 512) { job = 1; yl = y - 256; }
    else              { job = 2; yl = y - 512; }
    int conv, ublk;
    if (LAYER == 1) {
        conv = job == 0 ? 2 : job == 1 ? 4 : 0;
        ublk = (job == 2) ? 256 + yl : yl;
    } else {
        conv = job == 0 ? 3 : job == 1 ? 5 : 1;
        ublk = job * 256 + yl;
    }
    const float* bias = job == 0 ? b_pp : job == 1 ? b_ep : b_dp;
    const float* wl   = job == 0 ? wl_pp : job == 1 ? wl_ep : wl_dp;
    float* Yout = job == 0 ? g_Yp : job == 1 ? g_Ye : g_Yd;
    const long rowOff = job == 0 ? 0 : job == 1 ? (long)NB * MAXF : 2L * NB * MAXF;

    const uint8_t* Ublk  = g_U + (long)ublk * UBLK_B;
    const uint8_t* Vbase = g_V + ((long)(conv * 4 + blockIdx.x) * 32) * 32768;

    if (tid < 128) {
        s_bias[tid] = bias[blockIdx.x * 128 + tid];
        if (LAYER == 2) s_wl[tid] = wl[blockIdx.x * 128 + tid];
    }

    // ---- flat-copy staging (fully coalesced sequential) ----
    auto stageA = [&](int it) {
        const uint32_t abuf = sb + (it % 3) * A_BUF;
        const uint8_t* src = Ublk + (long)it * 16384;
#pragma unroll
        for (int qd = 0; qd < 4; qd++) {
            int j = tid + qd * 256;
            cpasync16(abuf + j * 16, src + j * 16);
        }
    };
    auto stageB = [&](int it) {
        const uint32_t bbuf = sb + B_BASE + (it % 3) * B_SLOT;
        const uint8_t* src = Vbase + (long)it * 32768;
#pragma unroll
        for (int qd = 0; qd < 8; qd++) {
            int j = tid + qd * 256;
            cpasync16(bbuf + j * 16, src + j * 16);
        }
    };

    // ---- per-lane ldmatrix bases ----
    const int q = lane >> 3;
    int am[2];
#pragma unroll
    for (int mt = 0; mt < 2; mt++) am[mt] = rowW + mt * 16 + ((q & 1) << 3) + (lane & 7);
    const int ac16b = q >> 1;
    int an[2];
#pragma unroll
    for (int np = 0; np < 2; np++) an[np] = colW + np * 16 + ((q >> 1) << 3) + (lane & 7);
    const int bc16b = q & 1;
    uint32_t aOff[2];
#pragma unroll
    for (int mt = 0; mt < 2; mt++) aOff[mt] = TADDR16(am[mt], ac16b);
    uint32_t bOff[2];
#pragma unroll
    for (int np = 0; np < 2; np++) bOff[np] = TADDR16(an[np], bc16b);

    float acc[4][2][4][4];              // [point][mtile][ntile][frag]
#pragma unroll
    for (int pt = 0; pt < 4; pt++)
#pragma unroll
        for (int mt = 0; mt < 2; mt++)
#pragma unroll
            for (int nt = 0; nt < 4; nt++)
#pragma unroll
                for (int v = 0; v < 4; v++) acc[pt][mt][nt][v] = 0.f;

    stageA(0); stageB(0); CP_COMMIT();
    stageA(1); stageB(1); CP_COMMIT();

    for (int it = 0; it < 32; it++) {
        CP_WAIT1();
        __syncthreads();
        const uint32_t aBuf = sb + (it % 3) * A_BUF;
        const uint32_t bBuf = sb + B_BASE + (it % 3) * B_SLOT;

#pragma unroll
        for (int pt = 0; pt < 4; pt++) {
            uint32_t ah[2][4], al[2][4];
#pragma unroll
            for (int mt = 0; mt < 2; mt++) {
                ldmx4(ah[mt], aBuf + pt * 4096 + aOff[mt]);
                ldmx4(al[mt], aBuf + pt * 4096 + 2048 + aOff[mt]);
            }
            uint32_t bh[4][2], bl[4][2];
#pragma unroll
            for (int np = 0; np < 2; np++) {
                uint32_t t[4];
                ldmx4(t, bBuf + pt * 8192 + bOff[np]);
                bh[2 * np][0] = t[0]; bh[2 * np][1] = t[1];
                bh[2 * np + 1][0] = t[2]; bh[2 * np + 1][1] = t[3];
                ldmx4(t, bBuf + pt * 8192 + 4096 + bOff[np]);
                bl[2 * np][0] = t[0]; bl[2 * np][1] = t[1];
                bl[2 * np + 1][0] = t[2]; bl[2 * np + 1][1] = t[3];
            }
#pragma unroll
            for (int mt = 0; mt < 2; mt++)
#pragma unroll
                for (int nt = 0; nt < 4; nt++) mma16816(acc[pt][mt][nt], ah[mt], bh[nt]);
#pragma unroll
            for (int mt = 0; mt < 2; mt++)
#pragma unroll
                for (int nt = 0; nt < 4; nt++) mma16816(acc[pt][mt][nt], ah[mt], bl[nt]);
#pragma unroll
            for (int mt = 0; mt < 2; mt++)
#pragma unroll
                for (int nt = 0; nt < 4; nt++) mma16816(acc[pt][mt][nt], al[mt], bh[nt]);
        }

        if (it + 2 < 32) { stageA(it + 2); stageB(it + 2); }
        CP_COMMIT();
    }

    // ---------------- epilogue: output transform + bias + relu ----------------
    const int tq = lane >> 2;
    const int tr = lane & 3;
    const int fBase = blockIdx.x * 128;
    if (LAYER == 1) {
#pragma unroll
        for (int mt = 0; mt < 2; mt++) {
#pragma unroll
            for (int nt = 0; nt < 4; nt++) {
                const int cl = colW + nt * 8 + 2 * tr;
                const float b0 = s_bias[cl], b1 = s_bias[cl + 1];
#pragma unroll
                for (int h = 0; h < 2; h++) {
                    const long P = (long)yl * 64 + rowW + mt * 16 + tq + 8 * h;
                    const int v0 = 2 * h, v1 = 2 * h + 1;
                    float m0a = acc[0][mt][nt][v0], m1a = acc[1][mt][nt][v0],
                          m2a = acc[2][mt][nt][v0], m3a = acc[3][mt][nt][v0];
                    float m0b = acc[0][mt][nt][v1], m1b = acc[1][mt][nt][v1],
                          m2b = acc[2][mt][nt][v1], m3b = acc[3][mt][nt][v1];
                    float y0a = fmaxf(m0a + m1a + m2a + b0, 0.f);
                    float y0b = fmaxf(m0b + m1b + m2b + b1, 0.f);
                    float y1a = fmaxf(m1a - m2a - m3a + b0, 0.f);
                    float y1b = fmaxf(m1b - m2b - m3b + b1, 0.f);
                    *(float2*)&Yout[(2 * P)     * 512 + fBase + cl] = make_float2(y0a, y0b);
                    *(float2*)&Yout[(2 * P + 1) * 512 + fBase + cl] = make_float2(y1a, y1b);
                }
            }
        }
    } else {
#pragma unroll
        for (int mt = 0; mt < 2; mt++) {
            float s00 = 0.f, s10 = 0.f, s01 = 0.f, s11 = 0.f;
#pragma unroll
            for (int nt = 0; nt < 4; nt++) {
                const int cl = colW + nt * 8 + 2 * tr;
                const float b0 = s_bias[cl], b1 = s_bias[cl + 1];
                const float w0 = s_wl[cl], w1 = s_wl[cl + 1];
#pragma unroll
                for (int h = 0; h < 2; h++) {
                    const int v0 = 2 * h, v1 = 2 * h + 1;
                    float m0a = acc[0][mt][nt][v0], m1a = acc[1][mt][nt][v0],
                          m2a = acc[2][mt][nt][v0], m3a = acc[3][mt][nt][v0];
                    float m0b = acc[0][mt][nt][v1], m1b = acc[1][mt][nt][v1],
                          m2b = acc[2][mt][nt][v1], m3b = acc[3][mt][nt][v1];
                    float sy0 = fmaxf(m0a + m1a + m2a + b0, 0.f) * w0
                              + fmaxf(m0b + m1b + m2b + b1, 0.f) * w1;
                    float sy1 = fmaxf(m1a - m2a - m3a + b0, 0.f) * w0
                              + fmaxf(m1b - m2b - m3b + b1, 0.f) * w1;
                    if (h == 0) { s00 += sy0; s10 += sy1; }
                    else        { s01 += sy0; s11 += sy1; }
                }
            }
            s00 += __shfl_xor_sync(0xFFFFFFFF, s00, 1);
            s00 += __shfl_xor_sync(0xFFFFFFFF, s00, 2);
            s10 += __shfl_xor_sync(0xFFFFFFFF, s10, 1);
            s10 += __shfl_xor_sync(0xFFFFFFFF, s10, 2);
            s01 += __shfl_xor_sync(0xFFFFFFFF, s01, 1);
            s01 += __shfl_xor_sync(0xFFFFFFFF, s01, 2);
            s11 += __shfl_xor_sync(0xFFFFFFFF, s11, 1);
            s11 += __shfl_xor_sync(0xFFFFFFFF, s11, 2);
            if (tr == 0) {
                int lr0 = 2 * (rowW + mt * 16 + tq);
                int lr1 = 2 * (rowW + mt * 16 + tq + 8);
                s_part[lr0][warpN]     = s00;
                s_part[lr0 + 1][warpN] = s10;
                s_part[lr1][warpN]     = s01;
                s_part[lr1 + 1][warpN] = s11;
            }
        }
        __syncthreads();
        if (tid < 128)
            g_part[(rowOff + (long)yl * 128 + tid) * 4 + blockIdx.x] =
                (s_part[tid][0] + s_part[tid][1]) + (s_part[tid][2] + s_part[tid][3]);
    }
}

// ---------------- merged final reduce: pp | ep | dp ----------------
__global__ void reduce_all_kernel(const float* __restrict__ pp_bl,
                                  const float* __restrict__ ep_bl,
                                  const float* __restrict__ dp_bl,
                                  float* __restrict__ outP,
                                  float* __restrict__ outE,
                                  float* __restrict__ outD) {
    int i = blockIdx.x * 256 + threadIdx.x;
    if (i >= TOTROWS) return;
    float s = (g_part[(long)i * 4 + 0] + g_part[(long)i * 4 + 1]) +
              (g_part[(long)i * 4 + 2] + g_part[(long)i * 4 + 3]);
    const int nPP = NB * MAXF, nPE = 2 * NB * MAXF;
    if (i < nPP)       outP[i]        = pp_bl[0] + s;
    else if (i < nPE)  outE[i - nPP]  = ep_bl[0] + s;
    else               outD[i - nPE]  = dp_bl[0] + s;
}

// ---------------- launch ----------------
extern "C" void kernel_launch(void* const* d_in, const int* in_sizes, int n_in,
                              void* d_out, int out_size) {
    const float* H     = (const float*)d_in[0];
    const int*   Dgt   = (const int*)  d_in[1];
    const float* Pgt   = (const float*)d_in[2];
    const float* Egt   = (const float*)d_in[3];
    const float* dp_w1 = (const float*)d_in[4];
    const float* dp_b1 = (const float*)d_in[5];
    const float* dp_w2 = (const float*)d_in[6];
    const float* dp_b2 = (const float*)d_in[7];
    const float* dp_wl = (const float*)d_in[8];
    const float* dp_bl = (const float*)d_in[9];
    const float* pp_w1 = (const float*)d_in[10];
    const float* pp_b1 = (const float*)d_in[11];
    const float* pp_w2 = (const float*)d_in[12];
    const float* pp_b2 = (const float*)d_in[13];
    const float* pp_wl = (const float*)d_in[14];
    const float* pp_bl = (const float*)d_in[15];
    const float* ep_w1 = (const float*)d_in[16];
    const float* ep_b1 = (const float*)d_in[17];
    const float* ep_w2 = (const float*)d_in[18];
    const float* ep_b2 = (const float*)d_in[19];
    const float* ep_wl = (const float*)d_in[20];
    const float* ep_bl = (const float*)d_in[21];
    const float* pw    = (const float*)d_in[22];
    const float* pb    = (const float*)d_in[23];
    const float* ew    = (const float*)d_in[24];
    const float* eb    = (const float*)d_in[25];

    float* out  = (float*)d_out;
    float* outH = out;                                   // (16,2048,512)
    float* outD = out + (long)NB * MAXF * DMODEL;        // (16,512)
    float* outP = outD + NB * SEQ;                       // (16,2048)
    float* outE = outP + NB * MAXF;                      // (16,2048)

    cudaFuncSetAttribute(conv_wino_kernel<1>, cudaFuncAttributeMaxDynamicSharedMemorySize, DSM_TOT);
    cudaFuncSetAttribute(conv_wino_kernel<2>, cudaFuncAttributeMaxDynamicSharedMemorySize, DSM_TOT);

    float* gHexp; cudaGetSymbolAddress((void**)&gHexp, g_Hexp);
    float* gYp;   cudaGetSymbolAddress((void**)&gYp, g_Yp);
    float* gYe;   cudaGetSymbolAddress((void**)&gYe, g_Ye);
    float* gYd;   cudaGetSymbolAddress((void**)&gYd, g_Yd);

    // 1: duration scan + Winograd weight transforms (merged)
    prep_kernel<<<16 + 768, 512>>>(Dgt, dp_w1, dp_w2, pp_w1, pp_w2, ep_w1, ep_w2);
    // 2: expand + adapt (fp32 Hexp + outH)
    gather_adapt_kernel<<<NB * MAXF, 128>>>(H, Pgt, Egt, pw, pb, ew, eb, outH);
    // 3: input transform layer 1: Hexp (U blocks 0..255) + H (256..319)
    utrans_kernel<<<320, 512>>>(gHexp, MAXF, 256, H, SEQ, 64, H, SEQ, 0);
    // 4: layer-1 convs (pp + ep + dp)  ← profiled slot
    conv_wino_kernel<1><<<dim3(4, 576), 256, DSM_TOT>>>(pp_b1, ep_b1, dp_b1,
                                                        nullptr, nullptr, nullptr);
    // 5: input transform layer 2: Yp (0..255) + Ye (256..511) + Yd (512..575)
    utrans_kernel<<<576, 512>>>(gYp, MAXF, 256, gYe, MAXF, 256, gYd, SEQ, 64);
    // 6: layer-2 convs + fused linear partials
    conv_wino_kernel<2><<<dim3(4, 576), 256, DSM_TOT>>>(pp_b2, ep_b2, dp_b2,
                                                        pp_wl, ep_wl, dp_wl);
    // 7: final reduce
    reduce_all_kernel<<<(TOTROWS + 255) / 256, 256>>>(pp_bl, ep_bl, dp_bl, outP, outE, outD);
}

// round 17
// speedup vs baseline: 1.4755x; 1.0009x over previous
#include <cuda_runtime.h>
#include <cuda_bf16.h>
#include <cstdint>

#define NB     16
#define SEQ    512
#define DMODEL 512
#define MAXF   2048

// ---------------- scratch (static __device__ arrays: allowed) ----------------
__device__ __align__(128) float g_Hexp[NB * MAXF * DMODEL];   // fp32 Hexp
__device__ __align__(128) float g_Yp  [NB * MAXF * DMODEL];   // pp layer1 out (fp32)
__device__ __align__(128) float g_Ye  [NB * MAXF * DMODEL];   // ep layer1 out
__device__ __align__(128) float g_Yd  [NB * SEQ  * DMODEL];   // dp layer1 out
// U: Winograd input tiles, PRE-SWIZZLED smem image:
//   [block(64 pairs)][chunk(32 x 16ch)][pt(4)][hl(2)][64pr x 16ch swizzled 2KB]
#define UBLK_B   524288L                 // 32 chunks x 16KB
__device__ __align__(128) uint8_t g_U[576 * UBLK_B];          // 302 MB
// V: Winograd weight tiles, PRE-SWIZZLED: [conv][xblk][chunk][pt][hl][128f x 16ch swizzled 4KB]
__device__ __align__(128) uint8_t g_V[6L * 4 * 32 * 32768];   // 25 MB
#define TOTROWS (2 * NB * MAXF + NB * SEQ)   // pp | ep | dp output rows
__device__ float g_part[TOTROWS * 4];
__device__ int   g_idx [NB * MAXF];

// ================= baseline-ISA helpers (compute_103-safe) =================
__device__ __forceinline__ uint32_t smem_to_u32(const void* p) {
    uint32_t a;
    asm("{ .reg .u64 t; cvta.to.shared.u64 t, %1; cvt.u32.u64 %0, t; }" : "=r"(a) : "l"(p));
    return a;
}
__device__ __forceinline__ void cpasync16(uint32_t dst, const void* src) {
    asm volatile("cp.async.cg.shared.global [%0], [%1], 16;" :: "r"(dst), "l"(src));
}
#define CP_COMMIT() asm volatile("cp.async.commit_group;" ::: "memory")
#define CP_WAIT1()  asm volatile("cp.async.wait_group 1;"  ::: "memory")

__device__ __forceinline__ void ldmx4(uint32_t* r, uint32_t addr) {
    asm volatile("ldmatrix.sync.aligned.m8n8.x4.shared.b16 {%0,%1,%2,%3}, [%4];"
                 : "=r"(r[0]), "=r"(r[1]), "=r"(r[2]), "=r"(r[3]) : "r"(addr));
}
__device__ __forceinline__ void mma16816(float* d, const uint32_t* a, const uint32_t* b) {
    asm volatile("mma.sync.aligned.m16n8k16.row.col.f32.bf16.bf16.f32 "
                 "{%0,%1,%2,%3}, {%4,%5,%6,%7}, {%8,%9}, {%0,%1,%2,%3};"
                 : "+f"(d[0]), "+f"(d[1]), "+f"(d[2]), "+f"(d[3])
                 : "r"(a[0]), "r"(a[1]), "r"(a[2]), "r"(a[3]), "r"(b[0]), "r"(b[1]));
}
__device__ __forceinline__ uint32_t pack2bf(float a, float b) {
    __nv_bfloat162 t = __floats2bfloat162_rn(a, b);
    return *reinterpret_cast<uint32_t*>(&t);
}
// packed tile addr: 4 rows per 128B line (row = 16ch bf16 = 2 x 16B segs), XOR swizzle
#define TADDR16(r, s) ((uint32_t)((((r) >> 2) * 128) + ((((((r) & 3) << 1) | (s)) ^ (((r) >> 2) & 7)) << 4)))

// ---------------- prep: duration scan (blocks 0..15) + Winograd weight transform ----------------
__global__ void prep_kernel(const int* __restrict__ Dgt,
                            const float* __restrict__ w0p, const float* __restrict__ w1p,
                            const float* __restrict__ w2p, const float* __restrict__ w3p,
                            const float* __restrict__ w4p, const float* __restrict__ w5p) {
    const int tid = threadIdx.x;
    if (blockIdx.x < 16) {
        __shared__ int cs[512];
        int b = blockIdx.x;
        int v = Dgt[b * 512 + tid];
        cs[tid] = v > 0 ? v : 0;
        __syncthreads();
        for (int off = 1; off < 512; off <<= 1) {
            int add = (tid >= off) ? cs[tid - off] : 0;
            __syncthreads();
            cs[tid] += add;
            __syncthreads();
        }
        int total = cs[511];
        int Tmax  = total < MAXF ? total : MAXF;
        for (int t = tid; t < MAXF; t += 512) {
            int r;
            if (t >= Tmax) {
                r = -1;
            } else {
                int lo = 0, hi = 511;
                while (lo < hi) {
                    int mid = (lo + hi) >> 1;
                    if (cs[mid] > t) hi = mid; else lo = mid + 1;
                }
                r = lo;
            }
            g_idx[b * MAXF + t] = r;
        }
        return;
    }
    int q = blockIdx.x - 16;          // 0..767
    int conv  = q >> 7;
    int xblk  = (q >> 5) & 3;
    int chunk = q & 31;
    const float* w = conv == 0 ? w0p : conv == 1 ? w1p : conv == 2 ? w2p :
                     conv == 3 ? w3p : conv == 4 ? w4p : w5p;
    int f_loc = tid >> 2, qq = tid & 3;
    int f = xblk * 128 + f_loc;
    int c = chunk * 16 + qq * 4;
    float V[4][4];
#pragma unroll
    for (int k = 0; k < 4; k++) {
        const float* wp = w + ((long)f * 512 + c + k) * 3;
        float w0 = wp[0], w1 = wp[1], w2 = wp[2];
        V[0][k] = w0;
        V[1][k] = 0.5f * (w0 + w1 + w2);
        V[2][k] = 0.5f * (w0 - w1 + w2);
        V[3][k] = w2;
    }
    uint8_t* dst = g_V + ((long)(conv * 4 + xblk) * 32 + chunk) * 32768;
    const uint32_t base = TADDR16(f_loc, qq >> 1) + (qq & 1) * 8;
#pragma unroll
    for (int pt = 0; pt < 4; pt++) {
        float h[4], l[4];
#pragma unroll
        for (int k = 0; k < 4; k++) {
            __nv_bfloat16 hb = __float2bfloat16(V[pt][k]);
            h[k] = __bfloat162float(hb);
            l[k] = V[pt][k] - h[k];
        }
        uint2 hv = make_uint2(pack2bf(h[0], h[1]), pack2bf(h[2], h[3]));
        uint2 lv = make_uint2(pack2bf(l[0], l[1]), pack2bf(l[2], l[3]));
        *(uint2*)(dst + pt * 8192 + base)        = hv;
        *(uint2*)(dst + pt * 8192 + 4096 + base) = lv;
    }
}

// ---------------- gather H_exp (fp32) + fused variance adapt ----------------
__global__ void gather_adapt_kernel(const float* __restrict__ H,
                                    const float* __restrict__ P,
                                    const float* __restrict__ E,
                                    const float* __restrict__ pw,
                                    const float* __restrict__ pb,
                                    const float* __restrict__ ew,
                                    const float* __restrict__ eb,
                                    float* __restrict__ outH) {
    int bt  = blockIdx.x;
    int b   = bt >> 11;
    int idx = g_idx[bt];
    int d   = threadIdx.x * 4;
    float4 h = make_float4(0.f, 0.f, 0.f, 0.f);
    if (idx >= 0) h = *(const float4*)&H[((long)(b * 512 + idx)) * 512 + d];
    long xo = (long)bt * 512 + d;
    *(float4*)&g_Hexp[xo] = h;

    float p = P[bt], e = E[bt];
    float4 pw4 = *(const float4*)&pw[d];
    float4 pb4 = *(const float4*)&pb[d];
    float4 ew4 = *(const float4*)&ew[d];
    float4 eb4 = *(const float4*)&eb[d];
    float4 o;
    o.x = h.x + p * pw4.x + pb4.x + e * ew4.x + eb4.x;
    o.y = h.y + p * pw4.y + pb4.y + e * ew4.y + eb4.y;
    o.z = h.z + p * pw4.z + pb4.z + e * ew4.z + eb4.z;
    o.w = h.w + p * pw4.w + pb4.w + e * ew4.w + eb4.w;
    *(float4*)&outH[xo] = o;
}

// ---------------- Winograd input transform -> pre-swizzled U blocks ----------------
__global__ void utrans_kernel(const float* __restrict__ A0, int S0, int n0,
                              const float* __restrict__ A1, int S1, int n1,
                              const float* __restrict__ A2, int S2, int n2) {
    int blk = blockIdx.x;
    const float* X; int S, loc;
    if (blk < n0)           { X = A0; S = S0; loc = blk; }
    else if (blk < n0 + n1) { X = A1; S = S1; loc = blk - n0; }
    else                    { X = A2; S = S2; loc = blk - n0 - n1; }
    const int ppb = S >> 1;
    const int pl  = loc * 64;
    const int b   = pl / ppb;
    const int p   = (pl - b * ppb) + (threadIdx.x >> 3);
    const int cg  = threadIdx.x & 7;
    const float* Xb = X + (long)b * S * 512 + cg * 2;

    const float* rp[4];
    bool av[4];
#pragma unroll
    for (int k = 0; k < 4; k++) {
        int s = 2 * p - 1 + k;
        av[k] = (s >= 0 && s < S);
        rp[k] = Xb + (long)(av[k] ? s : 0) * 512;
    }
    uint8_t* dstblk = g_U + (long)blk * UBLK_B;
    const uint32_t base = TADDR16(threadIdx.x >> 3, cg >> 2) + (cg & 3) * 4;

    for (int ch = 0; ch < 32; ch++) {
        float2 d[4];
#pragma unroll
        for (int k = 0; k < 4; k++)
            d[k] = av[k] ? *(const float2*)(rp[k] + ch * 16) : make_float2(0.f, 0.f);
        float U[4][2];
        U[0][0] = d[0].x - d[2].x;  U[0][1] = d[0].y - d[2].y;
        U[1][0] = d[1].x + d[2].x;  U[1][1] = d[1].y + d[2].y;
        U[2][0] = d[2].x - d[1].x;  U[2][1] = d[2].y - d[1].y;
        U[3][0] = d[1].x - d[3].x;  U[3][1] = d[1].y - d[3].y;
        uint8_t* dc = dstblk + (long)ch * 16384;
#pragma unroll
        for (int pt = 0; pt < 4; pt++) {
            __nv_bfloat16 h0 = __float2bfloat16(U[pt][0]);
            __nv_bfloat16 h1 = __float2bfloat16(U[pt][1]);
            float l0 = U[pt][0] - __bfloat162float(h0);
            float l1 = U[pt][1] - __bfloat162float(h1);
            __nv_bfloat162 hp = __halves2bfloat162(h0, h1);
            *(uint32_t*)(dc + pt * 4096 + base)        = *(uint32_t*)&hp;
            *(uint32_t*)(dc + pt * 4096 + 2048 + base) = pack2bf(l0, l1);
        }
    }
}

// ---------------- Winograd F(2,3) conv: 32x32 warp tiles + pt software pipelining ----------------
// Merged pp+ep+dp. Grid (4, 576). CTA: 64 pairs x 128 filters, 256 threads
// (8 warps 2M x 4N, warp 32pr x 32f, acc 128 fp32/thread).
// Mainloop: ah/bh fragments of pt+1 prefetched during pt's MMA groups -> the only
// exposed LDSM->MMA dependency is pt0 after the barrier (once per chunk).
#define A_BUF   16384
#define B_BASE  49152
#define B_SLOT  32768
#define DSM_TOT (B_BASE + 3 * B_SLOT)   // 147456

template <int LAYER>
__global__ __launch_bounds__(256, 1)
void conv_wino_kernel(const float* __restrict__ b_pp, const float* __restrict__ b_ep,
                      const float* __restrict__ b_dp, const float* __restrict__ wl_pp,
                      const float* __restrict__ wl_ep, const float* __restrict__ wl_dp) {
    extern __shared__ char sm[];
    const uint32_t sb = smem_to_u32(sm);
    __shared__ float s_bias[128];
    __shared__ float s_wl[128];
    __shared__ float s_part[128][4];

    const int tid  = threadIdx.x;
    const int lane = tid & 31;
    const int wid  = tid >> 5;
    const int warpM = wid & 1, warpN = wid >> 1;   // 2M x 4N
    const int rowW = warpM * 32;
    const int colW = warpN * 32;

    // ---- job decode ----
    const int y = blockIdx.y;
    int job, yl;
    if (y < 256)      { job = 0; yl = y; }
    else if (y < 512) { job = 1; yl = y - 256; }
    else              { job = 2; yl = y - 512; }
    int conv, ublk;
    if (LAYER == 1) {
        conv = job == 0 ? 2 : job == 1 ? 4 : 0;
        ublk = (job == 2) ? 256 + yl : yl;
    } else {
        conv = job == 0 ? 3 : job == 1 ? 5 : 1;
        ublk = job * 256 + yl;
    }
    const float* bias = job == 0 ? b_pp : job == 1 ? b_ep : b_dp;
    const float* wl   = job == 0 ? wl_pp : job == 1 ? wl_ep : wl_dp;
    float* Yout = job == 0 ? g_Yp : job == 1 ? g_Ye : g_Yd;
    const long rowOff = job == 0 ? 0 : job == 1 ? (long)NB * MAXF : 2L * NB * MAXF;

    const uint8_t* Ublk  = g_U + (long)ublk * UBLK_B;
    const uint8_t* Vbase = g_V + ((long)(conv * 4 + blockIdx.x) * 32) * 32768;

    if (tid < 128) {
        s_bias[tid] = bias[blockIdx.x * 128 + tid];
        if (LAYER == 2) s_wl[tid] = wl[blockIdx.x * 128 + tid];
    }

    // ---- flat-copy staging (fully coalesced sequential) ----
    auto stageA = [&](int it) {
        const uint32_t abuf = sb + (it % 3) * A_BUF;
        const uint8_t* src = Ublk + (long)it * 16384;
#pragma unroll
        for (int qd = 0; qd < 4; qd++) {
            int j = tid + qd * 256;
            cpasync16(abuf + j * 16, src + j * 16);
        }
    };
    auto stageB = [&](int it) {
        const uint32_t bbuf = sb + B_BASE + (it % 3) * B_SLOT;
        const uint8_t* src = Vbase + (long)it * 32768;
#pragma unroll
        for (int qd = 0; qd < 8; qd++) {
            int j = tid + qd * 256;
            cpasync16(bbuf + j * 16, src + j * 16);
        }
    };

    // ---- per-lane ldmatrix bases ----
    const int q = lane >> 3;
    int am[2];
#pragma unroll
    for (int mt = 0; mt < 2; mt++) am[mt] = rowW + mt * 16 + ((q & 1) << 3) + (lane & 7);
    const int ac16b = q >> 1;
    int an[2];
#pragma unroll
    for (int np = 0; np < 2; np++) an[np] = colW + np * 16 + ((q >> 1) << 3) + (lane & 7);
    const int bc16b = q & 1;
    uint32_t aOff[2];
#pragma unroll
    for (int mt = 0; mt < 2; mt++) aOff[mt] = TADDR16(am[mt], ac16b);
    uint32_t bOff[2];
#pragma unroll
    for (int np = 0; np < 2; np++) bOff[np] = TADDR16(an[np], bc16b);

    float acc[4][2][4][4];              // [point][mtile][ntile][frag]
#pragma unroll
    for (int pt = 0; pt < 4; pt++)
#pragma unroll
        for (int mt = 0; mt < 2; mt++)
#pragma unroll
            for (int nt = 0; nt < 4; nt++)
#pragma unroll
                for (int v = 0; v < 4; v++) acc[pt][mt][nt][v] = 0.f;

    stageA(0); stageB(0); CP_COMMIT();
    stageA(1); stageB(1); CP_COMMIT();

    // double-buffered hi fragments; lo fragments single-buffered
    uint32_t ah[2][2][4], bh[2][4][2];
    uint32_t al[2][4], bl[4][2];

    for (int it = 0; it < 32; it++) {
        CP_WAIT1();
        __syncthreads();
        const uint32_t aBuf = sb + (it % 3) * A_BUF;
        const uint32_t bBuf = sb + B_BASE + (it % 3) * B_SLOT;

        // prologue: hi fragments for pt 0
#pragma unroll
        for (int mt = 0; mt < 2; mt++) ldmx4(ah[0][mt], aBuf + aOff[mt]);
#pragma unroll
        for (int np = 0; np < 2; np++) {
            uint32_t t[4];
            ldmx4(t, bBuf + bOff[np]);
            bh[0][2 * np][0] = t[0]; bh[0][2 * np][1] = t[1];
            bh[0][2 * np + 1][0] = t[2]; bh[0][2 * np + 1][1] = t[3];
        }

#pragma unroll
        for (int pt = 0; pt < 4; pt++) {
            const int cur = pt & 1, nxt = cur ^ 1;
            // lo fragments of current pt (first use is 8+ MMAs away)
#pragma unroll
            for (int mt = 0; mt < 2; mt++)
                ldmx4(al[mt], aBuf + pt * 4096 + 2048 + aOff[mt]);
#pragma unroll
            for (int np = 0; np < 2; np++) {
                uint32_t t[4];
                ldmx4(t, bBuf + pt * 8192 + 4096 + bOff[np]);
                bl[2 * np][0] = t[0]; bl[2 * np][1] = t[1];
                bl[2 * np + 1][0] = t[2]; bl[2 * np + 1][1] = t[3];
            }
            // group 1: hh (operands prefetched)
#pragma unroll
            for (int mt = 0; mt < 2; mt++)
#pragma unroll
                for (int nt = 0; nt < 4; nt++) mma16816(acc[pt][mt][nt], ah[cur][mt], bh[cur][nt]);
            // prefetch hi fragments of pt+1 during the MMA storm
            if (pt < 3) {
#pragma unroll
                for (int mt = 0; mt < 2; mt++)
                    ldmx4(ah[nxt][mt], aBuf + (pt + 1) * 4096 + aOff[mt]);
#pragma unroll
                for (int np = 0; np < 2; np++) {
                    uint32_t t[4];
                    ldmx4(t, bBuf + (pt + 1) * 8192 + bOff[np]);
                    bh[nxt][2 * np][0] = t[0]; bh[nxt][2 * np][1] = t[1];
                    bh[nxt][2 * np + 1][0] = t[2]; bh[nxt][2 * np + 1][1] = t[3];
                }
            }
            // group 2: hl
#pragma unroll
            for (int mt = 0; mt < 2; mt++)
#pragma unroll
                for (int nt = 0; nt < 4; nt++) mma16816(acc[pt][mt][nt], ah[cur][mt], bl[nt]);
            // group 3: lh
#pragma unroll
            for (int mt = 0; mt < 2; mt++)
#pragma unroll
                for (int nt = 0; nt < 4; nt++) mma16816(acc[pt][mt][nt], al[mt], bh[cur][nt]);
        }

        if (it + 2 < 32) { stageA(it + 2); stageB(it + 2); }
        CP_COMMIT();
    }

    // ---------------- epilogue: output transform + bias + relu ----------------
    const int tq = lane >> 2;
    const int tr = lane & 3;
    const int fBase = blockIdx.x * 128;
    if (LAYER == 1) {
#pragma unroll
        for (int mt = 0; mt < 2; mt++) {
#pragma unroll
            for (int nt = 0; nt < 4; nt++) {
                const int cl = colW + nt * 8 + 2 * tr;
                const float b0 = s_bias[cl], b1 = s_bias[cl + 1];
#pragma unroll
                for (int h = 0; h < 2; h++) {
                    const long P = (long)yl * 64 + rowW + mt * 16 + tq + 8 * h;
                    const int v0 = 2 * h, v1 = 2 * h + 1;
                    float m0a = acc[0][mt][nt][v0], m1a = acc[1][mt][nt][v0],
                          m2a = acc[2][mt][nt][v0], m3a = acc[3][mt][nt][v0];
                    float m0b = acc[0][mt][nt][v1], m1b = acc[1][mt][nt][v1],
                          m2b = acc[2][mt][nt][v1], m3b = acc[3][mt][nt][v1];
                    float y0a = fmaxf(m0a + m1a + m2a + b0, 0.f);
                    float y0b = fmaxf(m0b + m1b + m2b + b1, 0.f);
                    float y1a = fmaxf(m1a - m2a - m3a + b0, 0.f);
                    float y1b = fmaxf(m1b - m2b - m3b + b1, 0.f);
                    *(float2*)&Yout[(2 * P)     * 512 + fBase + cl] = make_float2(y0a, y0b);
                    *(float2*)&Yout[(2 * P + 1) * 512 + fBase + cl] = make_float2(y1a, y1b);
                }
            }
        }
    } else {
#pragma unroll
        for (int mt = 0; mt < 2; mt++) {
            float s00 = 0.f, s10 = 0.f, s01 = 0.f, s11 = 0.f;
#pragma unroll
            for (int nt = 0; nt < 4; nt++) {
                const int cl = colW + nt * 8 + 2 * tr;
                const float b0 = s_bias[cl], b1 = s_bias[cl + 1];
                const float w0 = s_wl[cl], w1 = s_wl[cl + 1];
#pragma unroll
                for (int h = 0; h < 2; h++) {
                    const int v0 = 2 * h, v1 = 2 * h + 1;
                    float m0a = acc[0][mt][nt][v0], m1a = acc[1][mt][nt][v0],
                          m2a = acc[2][mt][nt][v0], m3a = acc[3][mt][nt][v0];
                    float m0b = acc[0][mt][nt][v1], m1b = acc[1][mt][nt][v1],
                          m2b = acc[2][mt][nt][v1], m3b = acc[3][mt][nt][v1];
                    float sy0 = fmaxf(m0a + m1a + m2a + b0, 0.f) * w0
                              + fmaxf(m0b + m1b + m2b + b1, 0.f) * w1;
                    float sy1 = fmaxf(m1a - m2a - m3a + b0, 0.f) * w0
                              + fmaxf(m1b - m2b - m3b + b1, 0.f) * w1;
                    if (h == 0) { s00 += sy0; s10 += sy1; }
                    else        { s01 += sy0; s11 += sy1; }
                }
            }
            s00 += __shfl_xor_sync(0xFFFFFFFF, s00, 1);
            s00 += __shfl_xor_sync(0xFFFFFFFF, s00, 2);
            s10 += __shfl_xor_sync(0xFFFFFFFF, s10, 1);
            s10 += __shfl_xor_sync(0xFFFFFFFF, s10, 2);
            s01 += __shfl_xor_sync(0xFFFFFFFF, s01, 1);
            s01 += __shfl_xor_sync(0xFFFFFFFF, s01, 2);
            s11 += __shfl_xor_sync(0xFFFFFFFF, s11, 1);
            s11 += __shfl_xor_sync(0xFFFFFFFF, s11, 2);
            if (tr == 0) {
                int lr0 = 2 * (rowW + mt * 16 + tq);
                int lr1 = 2 * (rowW + mt * 16 + tq + 8);
                s_part[lr0][warpN]     = s00;
                s_part[lr0 + 1][warpN] = s10;
                s_part[lr1][warpN]     = s01;
                s_part[lr1 + 1][warpN] = s11;
            }
        }
        __syncthreads();
        if (tid < 128)
            g_part[(rowOff + (long)yl * 128 + tid) * 4 + blockIdx.x] =
                (s_part[tid][0] + s_part[tid][1]) + (s_part[tid][2] + s_part[tid][3]);
    }
}

// ---------------- merged final reduce: pp | ep | dp ----------------
__global__ void reduce_all_kernel(const float* __restrict__ pp_bl,
                                  const float* __restrict__ ep_bl,
                                  const float* __restrict__ dp_bl,
                                  float* __restrict__ outP,
                                  float* __restrict__ outE,
                                  float* __restrict__ outD) {
    int i = blockIdx.x * 256 + threadIdx.x;
    if (i >= TOTROWS) return;
    float s = (g_part[(long)i * 4 + 0] + g_part[(long)i * 4 + 1]) +
              (g_part[(long)i * 4 + 2] + g_part[(long)i * 4 + 3]);
    const int nPP = NB * MAXF, nPE = 2 * NB * MAXF;
    if (i < nPP)       outP[i]        = pp_bl[0] + s;
    else if (i < nPE)  outE[i - nPP]  = ep_bl[0] + s;
    else               outD[i - nPE]  = dp_bl[0] + s;
}

// ---------------- launch ----------------
extern "C" void kernel_launch(void* const* d_in, const int* in_sizes, int n_in,
                              void* d_out, int out_size) {
    const float* H     = (const float*)d_in[0];
    const int*   Dgt   = (const int*)  d_in[1];
    const float* Pgt   = (const float*)d_in[2];
    const float* Egt   = (const float*)d_in[3];
    const float* dp_w1 = (const float*)d_in[4];
    const float* dp_b1 = (const float*)d_in[5];
    const float* dp_w2 = (const float*)d_in[6];
    const float* dp_b2 = (const float*)d_in[7];
    const float* dp_wl = (const float*)d_in[8];
    const float* dp_bl = (const float*)d_in[9];
    const float* pp_w1 = (const float*)d_in[10];
    const float* pp_b1 = (const float*)d_in[11];
    const float* pp_w2 = (const float*)d_in[12];
    const float* pp_b2 = (const float*)d_in[13];
    const float* pp_wl = (const float*)d_in[14];
    const float* pp_bl = (const float*)d_in[15];
    const float* ep_w1 = (const float*)d_in[16];
    const float* ep_b1 = (const float*)d_in[17];
    const float* ep_w2 = (const float*)d_in[18];
    const float* ep_b2 = (const float*)d_in[19];
    const float* ep_wl = (const float*)d_in[20];
    const float* ep_bl = (const float*)d_in[21];
    const float* pw    = (const float*)d_in[22];
    const float* pb    = (const float*)d_in[23];
    const float* ew    = (const float*)d_in[24];
    const float* eb    = (const float*)d_in[25];

    float* out  = (float*)d_out;
    float* outH = out;                                   // (16,2048,512)
    float* outD = out + (long)NB * MAXF * DMODEL;        // (16,512)
    float* outP = outD + NB * SEQ;                       // (16,2048)
    float* outE = outP + NB * MAXF;                      // (16,2048)

    cudaFuncSetAttribute(conv_wino_kernel<1>, cudaFuncAttributeMaxDynamicSharedMemorySize, DSM_TOT);
    cudaFuncSetAttribute(conv_wino_kernel<2>, cudaFuncAttributeMaxDynamicSharedMemorySize, DSM_TOT);

    float* gHexp; cudaGetSymbolAddress((void**)&gHexp, g_Hexp);
    float* gYp;   cudaGetSymbolAddress((void**)&gYp, g_Yp);
    float* gYe;   cudaGetSymbolAddress((void**)&gYe, g_Ye);
    float* gYd;   cudaGetSymbolAddress((void**)&gYd, g_Yd);

    // 1: duration scan + Winograd weight transforms (merged)
    prep_kernel<<<16 + 768, 512>>>(Dgt, dp_w1, dp_w2, pp_w1, pp_w2, ep_w1, ep_w2);
    // 2: expand + adapt (fp32 Hexp + outH)
    gather_adapt_kernel<<<NB * MAXF, 128>>>(H, Pgt, Egt, pw, pb, ew, eb, outH);
    // 3: input transform layer 1: Hexp (U blocks 0..255) + H (256..319)
    utrans_kernel<<<320, 512>>>(gHexp, MAXF, 256, H, SEQ, 64, H, SEQ, 0);
    // 4: layer-1 convs (pp + ep + dp)  ← profiled slot
    conv_wino_kernel<1><<<dim3(4, 576), 256, DSM_TOT>>>(pp_b1, ep_b1, dp_b1,
                                                        nullptr, nullptr, nullptr);
    // 5: input transform layer 2: Yp (0..255) + Ye (256..511) + Yd (512..575)
    utrans_kernel<<<576, 512>>>(gYp, MAXF, 256, gYe, MAXF, 256, gYd, SEQ, 64);
    // 6: layer-2 convs + fused linear partials
    conv_wino_kernel<2><<<dim3(4, 576), 256, DSM_TOT>>>(pp_b2, ep_b2, dp_b2,
                                                        pp_wl, ep_wl, dp_wl);
    // 7: final reduce
    reduce_all_kernel<<<(TOTROWS + 255) / 256, 256>>>(pp_bl, ep_bl, dp_bl, outP, outE, outD);
}